// round 12
// baseline (speedup 1.0000x reference)
#include <cuda_runtime.h>
#include <cuda_bf16.h>
#include <math.h>
#include <stdint.h>

#define D 64
#define N_MAX 327680
#define S_MAX 16384

// ---- scratch ----
__device__ float g_hA  [N_MAX * D];   // final h after both layers (+relu)
__device__ int   g_inedge[N_MAX];
__device__ double g_acc[2];
__device__ __align__(16) uint16_t g_gruBb[256 * 128];   // bf16 gate-interleaved [c=4j+g][k]
__device__ __align__(16) uint16_t g_msgGb[2 * 64 * 64]; // bf16 [layer][col j][k]
__device__ __align__(16) uint16_t g_w2Bb [64 * 64];     // bf16 [j][k]

// ---------------------------------------------------------------- helpers
__device__ __forceinline__ float fsigmoid(float x) {
    float e = __expf(-x);
    float r;
    asm("rcp.approx.f32 %0, %1;" : "=f"(r) : "f"(1.f + e));
    return r;
}
__device__ __forceinline__ float ftanh_(float x) {
    float t;
    asm("tanh.approx.f32 %0, %1;" : "=f"(t) : "f"(x));
    return t;
}
__device__ __forceinline__ uint32_t pbf2(float lo, float hi) {
    uint32_t o;
    asm("cvt.rn.bf16x2.f32 %0, %1, %2;" : "=r"(o) : "f"(hi), "f"(lo));
    return o;
}
__device__ __forceinline__ float bf2f(uint16_t u) {
    return __uint_as_float(((uint32_t)u) << 16);
}
__device__ __forceinline__ uint32_t smem_u32(const void* p) {
    return (uint32_t)__cvta_generic_to_shared(p);
}
__device__ __forceinline__ void cp16(uint32_t dst, const void* src) {
    asm volatile("cp.async.cg.shared.global [%0], [%1], 16;" :: "r"(dst), "l"(src));
}
__device__ __forceinline__ void mma_bf16(float d[4], const uint32_t a[4],
                                         uint32_t b0, uint32_t b1)
{
    asm volatile(
        "mma.sync.aligned.m16n8k16.row.col.f32.bf16.bf16.f32 "
        "{%0,%1,%2,%3}, {%4,%5,%6,%7}, {%8,%9}, {%0,%1,%2,%3};"
        : "+f"(d[0]), "+f"(d[1]), "+f"(d[2]), "+f"(d[3])
        : "r"(a[0]), "r"(a[1]), "r"(a[2]), "r"(a[3]), "r"(b0), "r"(b1));
}

// ------------------------------------- merged init: prepack + zero
__global__ void init_all(const float* __restrict__ W_ih, const float* __restrict__ W_hh,
                         const float* __restrict__ ggc, const float* __restrict__ W2,
                         int N)
{
    int i = blockIdx.x * blockDim.x + threadIdx.x;
    if (i < 256 * 128) {
        int c = i >> 7, k = i & 127;
        int j = c >> 2, g = c & 3;
        float v;
        if (g == 0)      v = (k < 64) ? W_ih[j * 64 + k]         : W_hh[j * 64 + (k - 64)];
        else if (g == 1) v = (k < 64) ? W_ih[(64 + j) * 64 + k]  : W_hh[(64 + j) * 64 + (k - 64)];
        else if (g == 2) v = (k < 64) ? W_ih[(128 + j) * 64 + k] : 0.f;
        else             v = (k < 64) ? 0.f                       : W_hh[(128 + j) * 64 + (k - 64)];
        g_gruBb[i] = __bfloat16_as_ushort(__float2bfloat16_rn(v));
    } else if (i < 256 * 128 + 2 * 4096) {
        int t = i - 256 * 128;
        int layer = t >> 12, r = t & 4095;
        int j = r >> 6, k = r & 63;
        g_msgGb[t] = __bfloat16_as_ushort(__float2bfloat16_rn(ggc[layer * 4096 + k * 64 + j]));
    } else if (i < 256 * 128 + 2 * 4096 + 4096) {
        int t = i - (256 * 128 + 2 * 4096);
        g_w2Bb[t] = __bfloat16_as_ushort(__float2bfloat16_rn(W2[t]));
    }
    if (i < 2) g_acc[i] = 0.0;
    if (i < N) g_inedge[i] = -1;
}
__global__ void build_inedge_kernel(const int* __restrict__ src,
                                    const int* __restrict__ dst, int E)
{
    int e = blockIdx.x * blockDim.x + threadIdx.x;
    if (e < E) g_inedge[dst[e]] = src[e];
}

// ============== single-kernel 2-layer GGC+GRU (80-row session-aligned tiles)
// smem (halfwords): sAgg[80][72] | sX0[80][72] | sX1[80][72] | sG[64][72] | sB[256][136]
#define XP 72
#define BKP 136
#define OF_X0  5760
#define OF_X1  11520
#define OF_G   17280
#define OF_B   21888
#define GNN_SMEM ((21888 + 256 * 136) * 2)

// phase-1: P = src @ sG, rowblock rb (16 rows), N=64, K=64, in-place
__device__ __forceinline__ void p1_tile(uint16_t* sSrc, uint16_t* sDst,
                                        const uint16_t* sG, int rb, int lr, int lk)
{
    int r0 = rb * 16 + lr;
    float p[8][4];
#pragma unroll
    for (int nt = 0; nt < 8; nt++)
#pragma unroll
        for (int q = 0; q < 4; q++) p[nt][q] = 0.f;
#pragma unroll
    for (int k0 = 0; k0 < 64; k0 += 16) {
        uint32_t a[4];
        a[0] = *(const uint32_t*)&sSrc[r0 * XP + k0 + 2 * lk];
        a[1] = *(const uint32_t*)&sSrc[(r0 + 8) * XP + k0 + 2 * lk];
        a[2] = *(const uint32_t*)&sSrc[r0 * XP + k0 + 8 + 2 * lk];
        a[3] = *(const uint32_t*)&sSrc[(r0 + 8) * XP + k0 + 8 + 2 * lk];
#pragma unroll
        for (int nt = 0; nt < 8; nt++) {
            int c = nt * 8 + lr;
            uint32_t b0 = *(const uint32_t*)&sG[c * XP + k0 + 2 * lk];
            uint32_t b1 = *(const uint32_t*)&sG[c * XP + k0 + 8 + 2 * lk];
            mma_bf16(p[nt], a, b0, b1);
        }
    }
#pragma unroll
    for (int nt = 0; nt < 8; nt++) {
        int c0 = nt * 8 + 2 * lk;
        *(uint32_t*)&sDst[r0 * XP + c0]       = pbf2(p[nt][0], p[nt][1]);
        *(uint32_t*)&sDst[(r0 + 8) * XP + c0] = pbf2(p[nt][2], p[nt][3]);
    }
}

__global__ void __launch_bounds__(256, 2) gnn2(
    const float* __restrict__ b_ih, const float* __restrict__ b_hh,
    int nrows, const float* __restrict__ emb, const int* __restrict__ items)
{
    extern __shared__ uint16_t sm[];
    uint16_t* sAgg = sm;
    uint16_t* sX0  = sm + OF_X0;
    uint16_t* sX1  = sm + OF_X1;
    uint16_t* sG   = sm + OF_G;
    uint16_t* sB   = sm + OF_B;

    int tid = threadIdx.x, lane = tid & 31, warp = tid >> 5;
    int lr = lane >> 2, lk = lane & 3;
    int rowBase = blockIdx.x * 80;

    // async weight loads
    for (int i = tid; i < 64 * 8; i += 256) {
        int c = i >> 3, q = (i & 7) * 8;
        cp16(smem_u32(&sG[c * XP + q]), &g_msgGb[c * 64 + q]);
    }
    asm volatile("cp.async.commit_group;");
    for (int i = tid; i < 256 * 16; i += 256) {
        int c = i >> 4, q = (i & 15) * 8;
        cp16(smem_u32(&sB[c * BKP + q]), &g_gruBb[c * 128 + q]);
    }
    asm volatile("cp.async.commit_group;");

    // sX0 = emb[items[gr]]
    for (int i = tid; i < 80 * 8; i += 256) {
        int rl = i >> 3, seg = (i & 7) * 8;
        int gr = rowBase + rl;
        float4 v0 = make_float4(0.f,0.f,0.f,0.f), v1 = v0;
        if (gr < nrows) {
            const float* sp = emb + (size_t)(__ldg(&items[gr]) - 1) * 64;
            v0 = *(const float4*)&sp[seg];
            v1 = *(const float4*)&sp[seg + 4];
        }
        uint32_t* dp = (uint32_t*)&sX0[rl * XP + seg];
        dp[0] = pbf2(v0.x, v0.y); dp[1] = pbf2(v0.z, v0.w);
        dp[2] = pbf2(v1.x, v1.y); dp[3] = pbf2(v1.z, v1.w);
    }
    __syncthreads();

    // sAgg = shift(sX0) masked by inedge (session-aligned: pred in-tile)
    for (int i = tid; i < 80 * 8; i += 256) {
        int rl = i >> 3, q = (i & 7) * 8;
        int gr = rowBase + rl;
        int p = (gr < nrows) ? __ldg(&g_inedge[gr]) : -1;
        uint4 z = make_uint4(0u, 0u, 0u, 0u);
        uint4 v = (p >= 0 && rl > 0) ? *(const uint4*)&sX0[(rl - 1) * XP + q] : z;
        *(uint4*)&sAgg[rl * XP + q] = v;
    }
    asm volatile("cp.async.wait_group 1;");   // sG ready
    __syncthreads();

    // layer 0 phase 1 (in place, rowblocks 0..4)
    if (warp < 5) p1_tile(sAgg, sAgg, sG, warp, lr, lk);
    asm volatile("cp.async.wait_group 0;");   // gruB ready
    __syncthreads();

    // layer 0 phase 2 + GRU epilogue -> sX1 (bf16 h0)
    for (int t = warp; t < 20; t += 8) {
        int rb = t >> 2, cb = t & 3;
        int r0 = rb * 16 + lr;
        int colW = cb * 64;
        float acc[8][4];
#pragma unroll
        for (int nt = 0; nt < 8; nt++)
#pragma unroll
            for (int q = 0; q < 4; q++) acc[nt][q] = 0.f;
#pragma unroll
        for (int kk = 0; kk < 8; kk++) {
            int k0 = kk * 16;
            const uint16_t* ab = (k0 < 64) ? sAgg : sX0;
            int kc = (k0 < 64) ? k0 : k0 - 64;
            uint32_t a[4];
            a[0] = *(const uint32_t*)&ab[r0 * XP + kc + 2 * lk];
            a[1] = *(const uint32_t*)&ab[(r0 + 8) * XP + kc + 2 * lk];
            a[2] = *(const uint32_t*)&ab[r0 * XP + kc + 8 + 2 * lk];
            a[3] = *(const uint32_t*)&ab[(r0 + 8) * XP + kc + 8 + 2 * lk];
#pragma unroll
            for (int nt = 0; nt < 8; nt++) {
                int c = colW + nt * 8 + lr;
                uint32_t b0 = *(const uint32_t*)&sB[c * BKP + k0 + 2 * lk];
                uint32_t b1 = *(const uint32_t*)&sB[c * BKP + k0 + 8 + 2 * lk];
                mma_bf16(acc[nt], a, b0, b1);
            }
        }
        int base_j = colW >> 2;
        int odd = lk & 1;
        int rg0 = rowBase + r0, rg1 = rg0 + 8;
        const float* hop0 = (rg0 < nrows) ? emb + (size_t)(__ldg(&items[rg0]) - 1) * 64 : nullptr;
        const float* hop1 = (rg1 < nrows) ? emb + (size_t)(__ldg(&items[rg1]) - 1) * 64 : nullptr;
#pragma unroll
        for (int nt = 0; nt < 8; nt++) {
            int j = base_j + 2 * nt + ((lk >> 1) & 1);
            float s0 = acc[nt][0], s1 = acc[nt][1], s2 = acc[nt][2], s3 = acc[nt][3];
            float e0 = __shfl_xor_sync(0xffffffffu, s0, 1);
            float e1 = __shfl_xor_sync(0xffffffffu, s1, 1);
            float e2 = __shfl_xor_sync(0xffffffffu, s2, 1);
            float e3 = __shfl_xor_sync(0xffffffffu, s3, 1);
            float xr0 = odd ? e0 : s0, xz0 = odd ? e1 : s1;
            float xi0 = odd ? s0 : e0, xn0 = odd ? s1 : e1;
            float xr1 = odd ? e2 : s2, xz1 = odd ? e3 : s3;
            float xi1 = odd ? s2 : e2, xn1 = odd ? s3 : e3;
            float br = __ldg(&b_ih[j])      + __ldg(&b_hh[j]);
            float bz = __ldg(&b_ih[64 + j]) + __ldg(&b_hh[64 + j]);
            float bi = __ldg(&b_ih[128 + j]);
            float bn = __ldg(&b_hh[128 + j]);
            float ho0 = hop0 ? hop0[j] : 0.f;
            float ho1 = hop1 ? hop1[j] : 0.f;
            float rr0 = fsigmoid(xr0 + br), zz0 = fsigmoid(xz0 + bz);
            float nn0 = ftanh_(fmaf(rr0, xn0 + bn, xi0 + bi));
            float v0 = fmaf(zz0, ho0 - nn0, nn0);
            float rr1 = fsigmoid(xr1 + br), zz1 = fsigmoid(xz1 + bz);
            float nn1 = ftanh_(fmaf(rr1, xn1 + bn, xi1 + bi));
            float v1 = fmaf(zz1, ho1 - nn1, nn1);
            float w0 = __shfl_xor_sync(0xffffffffu, v0, 2);
            float w1 = __shfl_xor_sync(0xffffffffu, v1, 2);
            if (lk == 0) {
                *(uint32_t*)&sX1[r0 * XP + j]       = pbf2(v0, w0);
                *(uint32_t*)&sX1[(r0 + 8) * XP + j] = pbf2(v1, w1);
            }
        }
    }
    __syncthreads();

    // reload sG (layer 1) + sAgg = shift(sX1)
    for (int i = tid; i < 64 * 8; i += 256) {
        int c = i >> 3, q = (i & 7) * 8;
        cp16(smem_u32(&sG[c * XP + q]), &g_msgGb[4096 + c * 64 + q]);
    }
    asm volatile("cp.async.commit_group;");
    for (int i = tid; i < 80 * 8; i += 256) {
        int rl = i >> 3, q = (i & 7) * 8;
        int gr = rowBase + rl;
        int p = (gr < nrows) ? __ldg(&g_inedge[gr]) : -1;
        uint4 z = make_uint4(0u, 0u, 0u, 0u);
        uint4 v = (p >= 0 && rl > 0) ? *(const uint4*)&sX1[(rl - 1) * XP + q] : z;
        *(uint4*)&sAgg[rl * XP + q] = v;
    }
    asm volatile("cp.async.wait_group 0;");
    __syncthreads();

    // layer 1 phase 1
    if (warp < 5) p1_tile(sAgg, sAgg, sG, warp, lr, lk);
    __syncthreads();

    // layer 1 phase 2 + GRU epilogue (+relu) -> g_hA
    for (int t = warp; t < 20; t += 8) {
        int rb = t >> 2, cb = t & 3;
        int r0 = rb * 16 + lr;
        int colW = cb * 64;
        float acc[8][4];
#pragma unroll
        for (int nt = 0; nt < 8; nt++)
#pragma unroll
            for (int q = 0; q < 4; q++) acc[nt][q] = 0.f;
#pragma unroll
        for (int kk = 0; kk < 8; kk++) {
            int k0 = kk * 16;
            const uint16_t* ab = (k0 < 64) ? sAgg : sX1;
            int kc = (k0 < 64) ? k0 : k0 - 64;
            uint32_t a[4];
            a[0] = *(const uint32_t*)&ab[r0 * XP + kc + 2 * lk];
            a[1] = *(const uint32_t*)&ab[(r0 + 8) * XP + kc + 2 * lk];
            a[2] = *(const uint32_t*)&ab[r0 * XP + kc + 8 + 2 * lk];
            a[3] = *(const uint32_t*)&ab[(r0 + 8) * XP + kc + 8 + 2 * lk];
#pragma unroll
            for (int nt = 0; nt < 8; nt++) {
                int c = colW + nt * 8 + lr;
                uint32_t b0 = *(const uint32_t*)&sB[c * BKP + k0 + 2 * lk];
                uint32_t b1 = *(const uint32_t*)&sB[c * BKP + k0 + 8 + 2 * lk];
                mma_bf16(acc[nt], a, b0, b1);
            }
        }
        int base_j = colW >> 2;
        int odd = lk & 1;
        int rg0 = rowBase + r0, rg1 = rg0 + 8;
#pragma unroll
        for (int nt = 0; nt < 8; nt++) {
            int j = base_j + 2 * nt + ((lk >> 1) & 1);
            float s0 = acc[nt][0], s1 = acc[nt][1], s2 = acc[nt][2], s3 = acc[nt][3];
            float e0 = __shfl_xor_sync(0xffffffffu, s0, 1);
            float e1 = __shfl_xor_sync(0xffffffffu, s1, 1);
            float e2 = __shfl_xor_sync(0xffffffffu, s2, 1);
            float e3 = __shfl_xor_sync(0xffffffffu, s3, 1);
            float xr0 = odd ? e0 : s0, xz0 = odd ? e1 : s1;
            float xi0 = odd ? s0 : e0, xn0 = odd ? s1 : e1;
            float xr1 = odd ? e2 : s2, xz1 = odd ? e3 : s3;
            float xi1 = odd ? s2 : e2, xn1 = odd ? s3 : e3;
            float br = __ldg(&b_ih[j])      + __ldg(&b_hh[j]);
            float bz = __ldg(&b_ih[64 + j]) + __ldg(&b_hh[64 + j]);
            float bi = __ldg(&b_ih[128 + j]);
            float bn = __ldg(&b_hh[128 + j]);
            float ho0 = bf2f(sX1[r0 * XP + j]);
            float ho1 = bf2f(sX1[(r0 + 8) * XP + j]);
            float rr0 = fsigmoid(xr0 + br), zz0 = fsigmoid(xz0 + bz);
            float nn0 = ftanh_(fmaf(rr0, xn0 + bn, xi0 + bi));
            float v0 = fmaxf(fmaf(zz0, ho0 - nn0, nn0), 0.f);
            float rr1 = fsigmoid(xr1 + br), zz1 = fsigmoid(xz1 + bz);
            float nn1 = ftanh_(fmaf(rr1, xn1 + bn, xi1 + bi));
            float v1 = fmaxf(fmaf(zz1, ho1 - nn1, nn1), 0.f);
            float w0 = __shfl_xor_sync(0xffffffffu, v0, 2);
            float w1 = __shfl_xor_sync(0xffffffffu, v1, 2);
            if (lk == 0) {
                if (rg0 < nrows) *(float2*)&g_hA[rg0 * 64 + j] = make_float2(v0, w0);
                if (rg1 < nrows) *(float2*)&g_hA[rg1 * 64 + j] = make_float2(v1, w1);
            }
        }
    }
}

// ============ attn_tail: vnW1 + hW2 + gate + s_g + s_h + BPR loss (4 sess/CTA)
// smem: sH bf16[80][72] | sW2 bf16[64][72] | sC f32[80][68] | sVn[4][64] |
//       sAl[80] | sSg[4][64] | sVnF[4][64] | sSh[4][64]
#define AT_SMEM (80*72*2 + 64*72*2 + 80*68*4 + 256*4 + 80*4 + 256*4 + 256*4 + 256*4)
__global__ void __launch_bounds__(256) attn_tail(
    const float* __restrict__ W1, const float* __restrict__ W3,
    const float* __restrict__ b1, const float* __restrict__ b2,
    const float* __restrict__ qw, const float* __restrict__ qb,
    const float* __restrict__ b3, const float* __restrict__ item_emb,
    const int* __restrict__ pos, const int* __restrict__ neg,
    int S, int L)
{
    extern __shared__ char smraw[];
    uint16_t* sH  = (uint16_t*)smraw;            // [80][72]
    uint16_t* sW2 = sH + 80 * 72;                // [64][72]
    float* sC  = (float*)(sW2 + 64 * 72);        // [80][68]
    float* sVn = sC + 80 * 68;                   // [4][64]
    float* sAl = sVn + 256;                      // [80]
    float* sSg = sAl + 80;                       // [4][64]
    float* sVnF= sSg + 256;                      // [4][64]
    float* sSh = sVnF + 256;                     // [4][64]

    int tid = threadIdx.x, lane = tid & 31, warp = tid >> 5;
    int lr = lane >> 2, lk = lane & 3;
    int s0 = blockIdx.x * 4;
    int rowBase = s0 * L;

    // fill sH (bf16 from g_hA) + sW2 async
    for (int i = tid; i < 80 * 8; i += 256) {
        int rl = i >> 3, seg = (i & 7) * 8;
        int gr = rowBase + rl;
        float4 v0 = *(const float4*)&g_hA[gr * 64 + seg];
        float4 v1 = *(const float4*)&g_hA[gr * 64 + seg + 4];
        uint32_t* dp = (uint32_t*)&sH[rl * 72 + seg];
        dp[0] = pbf2(v0.x, v0.y); dp[1] = pbf2(v0.z, v0.w);
        dp[2] = pbf2(v1.x, v1.y); dp[3] = pbf2(v1.z, v1.w);
    }
    for (int i = tid; i < 64 * 8; i += 256) {
        int c = i >> 3, q = (i & 7) * 8;
        cp16(smem_u32(&sW2[c * 72 + q]), &g_w2Bb[c * 64 + q]);
    }
    asm volatile("cp.async.commit_group;");
    asm volatile("cp.async.wait_group 0;");
    __syncthreads();

    // warps 0-4: hW2 mma -> sC fp32;  warps 5-7: vnW1 -> sVn
    if (warp < 5) {
        int r0 = warp * 16 + lr;
        float acc[8][4];
#pragma unroll
        for (int nt = 0; nt < 8; nt++)
#pragma unroll
            for (int q = 0; q < 4; q++) acc[nt][q] = 0.f;
#pragma unroll
        for (int k0 = 0; k0 < 64; k0 += 16) {
            uint32_t a[4];
            a[0] = *(const uint32_t*)&sH[r0 * 72 + k0 + 2 * lk];
            a[1] = *(const uint32_t*)&sH[(r0 + 8) * 72 + k0 + 2 * lk];
            a[2] = *(const uint32_t*)&sH[r0 * 72 + k0 + 8 + 2 * lk];
            a[3] = *(const uint32_t*)&sH[(r0 + 8) * 72 + k0 + 8 + 2 * lk];
#pragma unroll
            for (int nt = 0; nt < 8; nt++) {
                int c = nt * 8 + lr;
                uint32_t b0 = *(const uint32_t*)&sW2[c * 72 + k0 + 2 * lk];
                uint32_t b1 = *(const uint32_t*)&sW2[c * 72 + k0 + 8 + 2 * lk];
                mma_bf16(acc[nt], a, b0, b1);
            }
        }
#pragma unroll
        for (int nt = 0; nt < 8; nt++) {
            int c0 = nt * 8 + 2 * lk;
            *(float2*)&sC[r0 * 68 + c0]       = make_float2(acc[nt][0], acc[nt][1]);
            *(float2*)&sC[(r0 + 8) * 68 + c0] = make_float2(acc[nt][2], acc[nt][3]);
        }
    } else {
        // vnW1[sess][c] = sum_k h[last][k] * W1[c][k]   (fp32 exact)
        for (int o = (warp - 5) * 32 + lane; o < 256; o += 96) {
            int sess = o >> 6, c = o & 63;
            const float* vp = &g_hA[(size_t)((s0 + sess) * L + L - 1) * 64];
            const float* wp = &W1[c * 64];
            float acc = 0.f;
#pragma unroll 8
            for (int k = 0; k < 64; k++) acc = fmaf(vp[k], __ldg(&wp[k]), acc);
            sVn[o] = acc;
        }
    }
    __syncthreads();

    // gate + alpha per row (warp per row, 2 cols/lane)
    for (int r = warp; r < 80; r += 8) {
        int sess = r / L;
        int j0 = lane, j1 = lane + 32;
        float x0 = sC[r * 68 + j0] + sVn[sess * 64 + j0] + __ldg(&b1[j0]) + __ldg(&b2[j0]);
        float x1 = sC[r * 68 + j1] + sVn[sess * 64 + j1] + __ldg(&b1[j1]) + __ldg(&b2[j1]);
        float a = fmaf(fsigmoid(x0), __ldg(&qw[j0]), fsigmoid(x1) * __ldg(&qw[j1]));
#pragma unroll
        for (int o = 16; o; o >>= 1) a += __shfl_xor_sync(0xffffffffu, a, o);
        if (lane == 0) sAl[r] = a + __ldg(&qb[0]);
    }
    __syncthreads();

    // s_g (fp32, no atomics) + v_n fp32
    {
        int sess = tid >> 6, c = tid & 63;
        int gr0 = (s0 + sess) * L;
        float sg = 0.f;
        for (int i2 = 0; i2 < L; i2++)
            sg = fmaf(sAl[sess * L + i2], g_hA[(size_t)(gr0 + i2) * 64 + c], sg);
        sSg[tid] = sg;
        sVnF[tid] = g_hA[(size_t)(gr0 + L - 1) * 64 + c];
    }
    __syncthreads();

    // s_h = [vn | sg] @ W3^T + b3
    {
        int sess = tid >> 6, c = tid & 63;
        const float* w3r = W3 + c * 128;
        float acc = __ldg(&b3[c]);
#pragma unroll 8
        for (int k = 0; k < 64; k++) acc = fmaf(sVnF[sess * 64 + k], __ldg(&w3r[k]), acc);
#pragma unroll 8
        for (int k = 0; k < 64; k++) acc = fmaf(sSg[sess * 64 + k], __ldg(&w3r[64 + k]), acc);
        sSh[tid] = acc;
    }
    __syncthreads();

    // BPR loss (warp per session)
    if (warp < 4) {
        int gs = s0 + warp;
        if (gs < S) {
            int ip = __ldg(&pos[gs]), in2 = __ldg(&neg[gs]);
            float pp = 0.f, np = 0.f, rg = 0.f;
#pragma unroll
            for (int t = 0; t < 2; t++) {
                int j = lane + t * 32;
                float sv = sSh[warp * 64 + j];
                float pe = __ldg(&item_emb[(size_t)ip * 64 + j]);
                float ne = __ldg(&item_emb[(size_t)in2 * 64 + j]);
                pp = fmaf(sv, pe, pp);
                np = fmaf(sv, ne, np);
                rg += sv * sv + pe * pe + ne * ne;
            }
#pragma unroll
            for (int o = 16; o; o >>= 1) {
                pp += __shfl_xor_sync(0xffffffffu, pp, o);
                np += __shfl_xor_sync(0xffffffffu, np, o);
                rg += __shfl_xor_sync(0xffffffffu, rg, o);
            }
            if (lane == 0) {
                float x = pp - np;
                float lsm = (x > 0.f) ? log1pf(expf(-x)) : (-x + log1pf(expf(x)));
                atomicAdd(&g_acc[0], (double)lsm);
                atomicAdd(&g_acc[1], (double)rg);
            }
        }
    }
}

__global__ void finalize_kernel(float* out, int out_size)
{
    double loss = g_acc[0];
    double nr = g_acc[1] * 1e-5;
    float t = (float)(loss + nr), l = (float)loss, r = (float)nr;
    if (out_size > 0) out[0] = t;
    if (out_size > 1) out[1] = l;
    if (out_size > 2) out[2] = r;
    if (out_size > 3) out[3] = r;
    if (out_size > 4) out[4] = r;
}

// ---------------------------------------------------------------- host
extern "C" void kernel_launch(void* const* d_in, const int* in_sizes, int n_in,
                              void* d_out, int out_size)
{
    const float* item_emb = (const float*)d_in[0];
    const float* ggc      = (const float*)d_in[1];
    const float* W_ih     = (const float*)d_in[2];
    const float* b_ih     = (const float*)d_in[3];
    const float* W_hh     = (const float*)d_in[4];
    const float* b_hh     = (const float*)d_in[5];
    const float* W1       = (const float*)d_in[6];
    const float* b1       = (const float*)d_in[7];
    const float* W2       = (const float*)d_in[8];
    const float* b2       = (const float*)d_in[9];
    const float* qw       = (const float*)d_in[10];
    const float* qb       = (const float*)d_in[11];
    const float* W3       = (const float*)d_in[12];
    const float* b3       = (const float*)d_in[13];
    const int* node_items = (const int*)d_in[14];
    const int* edge_index = (const int*)d_in[15];
    const int* pos        = (const int*)d_in[17];
    const int* neg        = (const int*)d_in[18];

    int N = in_sizes[14];
    int E = in_sizes[15] / 2;
    int S = in_sizes[17];
    int L = N / S;                       // 20 for this problem instance
    float* out = (float*)d_out;

    cudaFuncSetAttribute(gnn2,      cudaFuncAttributeMaxDynamicSharedMemorySize, GNN_SMEM);
    cudaFuncSetAttribute(attn_tail, cudaFuncAttributeMaxDynamicSharedMemorySize, AT_SMEM);

    const int* src = edge_index;
    const int* dst = edge_index + E;

    init_all<<<(N + 255) / 256, 256>>>(W_ih, W_hh, ggc, W2, N);
    build_inedge_kernel<<<(E + 255) / 256, 256>>>(src, dst, E);

    gnn2<<<(N + 79) / 80, 256, GNN_SMEM>>>(b_ih, b_hh, N, item_emb, node_items);

    attn_tail<<<(S + 3) / 4, 256, AT_SMEM>>>(W1, W3, b1, b2, qw, qb, b3,
                                             item_emb, pos, neg, S, L);
    finalize_kernel<<<1, 1>>>(out, out_size);
}

// round 13
// speedup vs baseline: 2.0993x; 2.0993x over previous
#include <cuda_runtime.h>
#include <cuda_bf16.h>
#include <math.h>
#include <stdint.h>

#define D 64
#define N_MAX 327680
#define S_MAX 16384

// ---- scratch ----
__device__ float g_hA  [N_MAX * D];   // final h after both layers (+relu)
__device__ int   g_inedge[N_MAX];
__device__ double g_acc[2];
__device__ __align__(16) uint16_t g_gruBb[256 * 128];   // bf16 gate-interleaved [c=4j+g][k]
__device__ __align__(16) uint16_t g_msgGb[2 * 64 * 64]; // bf16 [layer][col j][k]
__device__ __align__(16) uint16_t g_w2Bb [64 * 64];     // bf16 [j][k]

// ---------------------------------------------------------------- helpers
__device__ __forceinline__ float fsigmoid(float x) {
    float e = __expf(-x);
    float r;
    asm("rcp.approx.f32 %0, %1;" : "=f"(r) : "f"(1.f + e));
    return r;
}
__device__ __forceinline__ float ftanh_(float x) {
    float t;
    asm("tanh.approx.f32 %0, %1;" : "=f"(t) : "f"(x));
    return t;
}
__device__ __forceinline__ uint32_t pbf2(float lo, float hi) {
    uint32_t o;
    asm("cvt.rn.bf16x2.f32 %0, %1, %2;" : "=r"(o) : "f"(hi), "f"(lo));
    return o;
}
__device__ __forceinline__ float bf2f(uint16_t u) {
    return __uint_as_float(((uint32_t)u) << 16);
}
__device__ __forceinline__ uint32_t smem_u32(const void* p) {
    return (uint32_t)__cvta_generic_to_shared(p);
}
__device__ __forceinline__ void cp16(uint32_t dst, const void* src) {
    asm volatile("cp.async.cg.shared.global [%0], [%1], 16;" :: "r"(dst), "l"(src));
}
__device__ __forceinline__ void mma_bf16(float d[4], const uint32_t a[4],
                                         uint32_t b0, uint32_t b1)
{
    asm volatile(
        "mma.sync.aligned.m16n8k16.row.col.f32.bf16.bf16.f32 "
        "{%0,%1,%2,%3}, {%4,%5,%6,%7}, {%8,%9}, {%0,%1,%2,%3};"
        : "+f"(d[0]), "+f"(d[1]), "+f"(d[2]), "+f"(d[3])
        : "r"(a[0]), "r"(a[1]), "r"(a[2]), "r"(a[3]), "r"(b0), "r"(b1));
}

// ------------------------------------- merged init: prepack + zero
__global__ void init_all(const float* __restrict__ W_ih, const float* __restrict__ W_hh,
                         const float* __restrict__ ggc, const float* __restrict__ W2,
                         int N)
{
    int i = blockIdx.x * blockDim.x + threadIdx.x;
    if (i < 256 * 128) {
        int c = i >> 7, k = i & 127;
        int j = c >> 2, g = c & 3;
        float v;
        if (g == 0)      v = (k < 64) ? W_ih[j * 64 + k]         : W_hh[j * 64 + (k - 64)];
        else if (g == 1) v = (k < 64) ? W_ih[(64 + j) * 64 + k]  : W_hh[(64 + j) * 64 + (k - 64)];
        else if (g == 2) v = (k < 64) ? W_ih[(128 + j) * 64 + k] : 0.f;
        else             v = (k < 64) ? 0.f                       : W_hh[(128 + j) * 64 + (k - 64)];
        g_gruBb[i] = __bfloat16_as_ushort(__float2bfloat16_rn(v));
    } else if (i < 256 * 128 + 2 * 4096) {
        int t = i - 256 * 128;
        int layer = t >> 12, r = t & 4095;
        int j = r >> 6, k = r & 63;
        g_msgGb[t] = __bfloat16_as_ushort(__float2bfloat16_rn(ggc[layer * 4096 + k * 64 + j]));
    } else if (i < 256 * 128 + 2 * 4096 + 4096) {
        int t = i - (256 * 128 + 2 * 4096);
        g_w2Bb[t] = __bfloat16_as_ushort(__float2bfloat16_rn(W2[t]));
    }
    if (i < 2) g_acc[i] = 0.0;
    if (i < N) g_inedge[i] = -1;
}
__global__ void build_inedge_kernel(const int* __restrict__ src,
                                    const int* __restrict__ dst, int E)
{
    int e = blockIdx.x * blockDim.x + threadIdx.x;
    if (e < E) g_inedge[dst[e]] = src[e];
}

// ============== single-kernel 2-layer GGC+GRU (80-row session-aligned tiles)
#define XP 72
#define BKP 136
#define OF_X0  5760
#define OF_X1  11520
#define OF_G   17280
#define OF_B   21888
#define GNN_SMEM ((21888 + 256 * 136) * 2)

__device__ __forceinline__ void p1_tile(uint16_t* sSrc, uint16_t* sDst,
                                        const uint16_t* sG, int rb, int lr, int lk)
{
    int r0 = rb * 16 + lr;
    float p[8][4];
#pragma unroll
    for (int nt = 0; nt < 8; nt++)
#pragma unroll
        for (int q = 0; q < 4; q++) p[nt][q] = 0.f;
#pragma unroll
    for (int k0 = 0; k0 < 64; k0 += 16) {
        uint32_t a[4];
        a[0] = *(const uint32_t*)&sSrc[r0 * XP + k0 + 2 * lk];
        a[1] = *(const uint32_t*)&sSrc[(r0 + 8) * XP + k0 + 2 * lk];
        a[2] = *(const uint32_t*)&sSrc[r0 * XP + k0 + 8 + 2 * lk];
        a[3] = *(const uint32_t*)&sSrc[(r0 + 8) * XP + k0 + 8 + 2 * lk];
#pragma unroll
        for (int nt = 0; nt < 8; nt++) {
            int c = nt * 8 + lr;
            uint32_t b0 = *(const uint32_t*)&sG[c * XP + k0 + 2 * lk];
            uint32_t b1 = *(const uint32_t*)&sG[c * XP + k0 + 8 + 2 * lk];
            mma_bf16(p[nt], a, b0, b1);
        }
    }
#pragma unroll
    for (int nt = 0; nt < 8; nt++) {
        int c0 = nt * 8 + 2 * lk;
        *(uint32_t*)&sDst[r0 * XP + c0]       = pbf2(p[nt][0], p[nt][1]);
        *(uint32_t*)&sDst[(r0 + 8) * XP + c0] = pbf2(p[nt][2], p[nt][3]);
    }
}

__global__ void __launch_bounds__(256, 2) gnn2(
    const float* __restrict__ b_ih, const float* __restrict__ b_hh,
    int nrows, const float* __restrict__ emb, const int* __restrict__ items)
{
    extern __shared__ uint16_t sm[];
    uint16_t* sAgg = sm;
    uint16_t* sX0  = sm + OF_X0;
    uint16_t* sX1  = sm + OF_X1;
    uint16_t* sG   = sm + OF_G;
    uint16_t* sB   = sm + OF_B;

    int tid = threadIdx.x, lane = tid & 31, warp = tid >> 5;
    int lr = lane >> 2, lk = lane & 3;
    int rowBase = blockIdx.x * 80;

    for (int i = tid; i < 64 * 8; i += 256) {
        int c = i >> 3, q = (i & 7) * 8;
        cp16(smem_u32(&sG[c * XP + q]), &g_msgGb[c * 64 + q]);
    }
    asm volatile("cp.async.commit_group;");
    for (int i = tid; i < 256 * 16; i += 256) {
        int c = i >> 4, q = (i & 15) * 8;
        cp16(smem_u32(&sB[c * BKP + q]), &g_gruBb[c * 128 + q]);
    }
    asm volatile("cp.async.commit_group;");

    for (int i = tid; i < 80 * 8; i += 256) {
        int rl = i >> 3, seg = (i & 7) * 8;
        int gr = rowBase + rl;
        float4 v0 = make_float4(0.f,0.f,0.f,0.f), v1 = v0;
        if (gr < nrows) {
            const float* sp = emb + (size_t)(__ldg(&items[gr]) - 1) * 64;
            v0 = *(const float4*)&sp[seg];
            v1 = *(const float4*)&sp[seg + 4];
        }
        uint32_t* dp = (uint32_t*)&sX0[rl * XP + seg];
        dp[0] = pbf2(v0.x, v0.y); dp[1] = pbf2(v0.z, v0.w);
        dp[2] = pbf2(v1.x, v1.y); dp[3] = pbf2(v1.z, v1.w);
    }
    __syncthreads();

    for (int i = tid; i < 80 * 8; i += 256) {
        int rl = i >> 3, q = (i & 7) * 8;
        int gr = rowBase + rl;
        int p = (gr < nrows) ? __ldg(&g_inedge[gr]) : -1;
        uint4 z = make_uint4(0u, 0u, 0u, 0u);
        uint4 v = (p >= 0 && rl > 0) ? *(const uint4*)&sX0[(rl - 1) * XP + q] : z;
        *(uint4*)&sAgg[rl * XP + q] = v;
    }
    asm volatile("cp.async.wait_group 1;");
    __syncthreads();

    if (warp < 5) p1_tile(sAgg, sAgg, sG, warp, lr, lk);
    asm volatile("cp.async.wait_group 0;");
    __syncthreads();

    // layer 0 phase 2 + GRU epilogue -> sX1
    for (int t = warp; t < 20; t += 8) {
        int rb = t >> 2, cb = t & 3;
        int r0 = rb * 16 + lr;
        int colW = cb * 64;
        float acc[8][4];
#pragma unroll
        for (int nt = 0; nt < 8; nt++)
#pragma unroll
            for (int q = 0; q < 4; q++) acc[nt][q] = 0.f;
#pragma unroll
        for (int kk = 0; kk < 8; kk++) {
            int k0 = kk * 16;
            const uint16_t* ab = (k0 < 64) ? sAgg : sX0;
            int kc = (k0 < 64) ? k0 : k0 - 64;
            uint32_t a[4];
            a[0] = *(const uint32_t*)&ab[r0 * XP + kc + 2 * lk];
            a[1] = *(const uint32_t*)&ab[(r0 + 8) * XP + kc + 2 * lk];
            a[2] = *(const uint32_t*)&ab[r0 * XP + kc + 8 + 2 * lk];
            a[3] = *(const uint32_t*)&ab[(r0 + 8) * XP + kc + 8 + 2 * lk];
#pragma unroll
            for (int nt = 0; nt < 8; nt++) {
                int c = colW + nt * 8 + lr;
                uint32_t b0 = *(const uint32_t*)&sB[c * BKP + k0 + 2 * lk];
                uint32_t b1 = *(const uint32_t*)&sB[c * BKP + k0 + 8 + 2 * lk];
                mma_bf16(acc[nt], a, b0, b1);
            }
        }
        int base_j = colW >> 2;
        int odd = lk & 1;
        int rg0 = rowBase + r0, rg1 = rg0 + 8;
        const float* hop0 = (rg0 < nrows) ? emb + (size_t)(__ldg(&items[rg0]) - 1) * 64 : nullptr;
        const float* hop1 = (rg1 < nrows) ? emb + (size_t)(__ldg(&items[rg1]) - 1) * 64 : nullptr;
#pragma unroll
        for (int nt = 0; nt < 8; nt++) {
            int j = base_j + 2 * nt + ((lk >> 1) & 1);
            float s0 = acc[nt][0], s1 = acc[nt][1], s2 = acc[nt][2], s3 = acc[nt][3];
            float e0 = __shfl_xor_sync(0xffffffffu, s0, 1);
            float e1 = __shfl_xor_sync(0xffffffffu, s1, 1);
            float e2 = __shfl_xor_sync(0xffffffffu, s2, 1);
            float e3 = __shfl_xor_sync(0xffffffffu, s3, 1);
            float xr0 = odd ? e0 : s0, xz0 = odd ? e1 : s1;
            float xi0 = odd ? s0 : e0, xn0 = odd ? s1 : e1;
            float xr1 = odd ? e2 : s2, xz1 = odd ? e3 : s3;
            float xi1 = odd ? s2 : e2, xn1 = odd ? s3 : e3;
            float br = __ldg(&b_ih[j])      + __ldg(&b_hh[j]);
            float bz = __ldg(&b_ih[64 + j]) + __ldg(&b_hh[64 + j]);
            float bi = __ldg(&b_ih[128 + j]);
            float bn = __ldg(&b_hh[128 + j]);
            float ho0 = hop0 ? hop0[j] : 0.f;
            float ho1 = hop1 ? hop1[j] : 0.f;
            float rr0 = fsigmoid(xr0 + br), zz0 = fsigmoid(xz0 + bz);
            float nn0 = ftanh_(fmaf(rr0, xn0 + bn, xi0 + bi));
            float v0 = fmaf(zz0, ho0 - nn0, nn0);
            float rr1 = fsigmoid(xr1 + br), zz1 = fsigmoid(xz1 + bz);
            float nn1 = ftanh_(fmaf(rr1, xn1 + bn, xi1 + bi));
            float v1 = fmaf(zz1, ho1 - nn1, nn1);
            float w0 = __shfl_xor_sync(0xffffffffu, v0, 2);
            float w1 = __shfl_xor_sync(0xffffffffu, v1, 2);
            if (lk == 0) {
                *(uint32_t*)&sX1[r0 * XP + j]       = pbf2(v0, w0);
                *(uint32_t*)&sX1[(r0 + 8) * XP + j] = pbf2(v1, w1);
            }
        }
    }
    __syncthreads();

    for (int i = tid; i < 64 * 8; i += 256) {
        int c = i >> 3, q = (i & 7) * 8;
        cp16(smem_u32(&sG[c * XP + q]), &g_msgGb[4096 + c * 64 + q]);
    }
    asm volatile("cp.async.commit_group;");
    for (int i = tid; i < 80 * 8; i += 256) {
        int rl = i >> 3, q = (i & 7) * 8;
        int gr = rowBase + rl;
        int p = (gr < nrows) ? __ldg(&g_inedge[gr]) : -1;
        uint4 z = make_uint4(0u, 0u, 0u, 0u);
        uint4 v = (p >= 0 && rl > 0) ? *(const uint4*)&sX1[(rl - 1) * XP + q] : z;
        *(uint4*)&sAgg[rl * XP + q] = v;
    }
    asm volatile("cp.async.wait_group 0;");
    __syncthreads();

    if (warp < 5) p1_tile(sAgg, sAgg, sG, warp, lr, lk);
    __syncthreads();

    // layer 1 phase 2 + GRU epilogue (+relu) -> g_hA
    for (int t = warp; t < 20; t += 8) {
        int rb = t >> 2, cb = t & 3;
        int r0 = rb * 16 + lr;
        int colW = cb * 64;
        float acc[8][4];
#pragma unroll
        for (int nt = 0; nt < 8; nt++)
#pragma unroll
            for (int q = 0; q < 4; q++) acc[nt][q] = 0.f;
#pragma unroll
        for (int kk = 0; kk < 8; kk++) {
            int k0 = kk * 16;
            const uint16_t* ab = (k0 < 64) ? sAgg : sX1;
            int kc = (k0 < 64) ? k0 : k0 - 64;
            uint32_t a[4];
            a[0] = *(const uint32_t*)&ab[r0 * XP + kc + 2 * lk];
            a[1] = *(const uint32_t*)&ab[(r0 + 8) * XP + kc + 2 * lk];
            a[2] = *(const uint32_t*)&ab[r0 * XP + kc + 8 + 2 * lk];
            a[3] = *(const uint32_t*)&ab[(r0 + 8) * XP + kc + 8 + 2 * lk];
#pragma unroll
            for (int nt = 0; nt < 8; nt++) {
                int c = colW + nt * 8 + lr;
                uint32_t b0 = *(const uint32_t*)&sB[c * BKP + k0 + 2 * lk];
                uint32_t b1 = *(const uint32_t*)&sB[c * BKP + k0 + 8 + 2 * lk];
                mma_bf16(acc[nt], a, b0, b1);
            }
        }
        int base_j = colW >> 2;
        int odd = lk & 1;
        int rg0 = rowBase + r0, rg1 = rg0 + 8;
#pragma unroll
        for (int nt = 0; nt < 8; nt++) {
            int j = base_j + 2 * nt + ((lk >> 1) & 1);
            float s0 = acc[nt][0], s1 = acc[nt][1], s2 = acc[nt][2], s3 = acc[nt][3];
            float e0 = __shfl_xor_sync(0xffffffffu, s0, 1);
            float e1 = __shfl_xor_sync(0xffffffffu, s1, 1);
            float e2 = __shfl_xor_sync(0xffffffffu, s2, 1);
            float e3 = __shfl_xor_sync(0xffffffffu, s3, 1);
            float xr0 = odd ? e0 : s0, xz0 = odd ? e1 : s1;
            float xi0 = odd ? s0 : e0, xn0 = odd ? s1 : e1;
            float xr1 = odd ? e2 : s2, xz1 = odd ? e3 : s3;
            float xi1 = odd ? s2 : e2, xn1 = odd ? s3 : e3;
            float br = __ldg(&b_ih[j])      + __ldg(&b_hh[j]);
            float bz = __ldg(&b_ih[64 + j]) + __ldg(&b_hh[64 + j]);
            float bi = __ldg(&b_ih[128 + j]);
            float bn = __ldg(&b_hh[128 + j]);
            float ho0 = bf2f(sX1[r0 * XP + j]);
            float ho1 = bf2f(sX1[(r0 + 8) * XP + j]);
            float rr0 = fsigmoid(xr0 + br), zz0 = fsigmoid(xz0 + bz);
            float nn0 = ftanh_(fmaf(rr0, xn0 + bn, xi0 + bi));
            float v0 = fmaxf(fmaf(zz0, ho0 - nn0, nn0), 0.f);
            float rr1 = fsigmoid(xr1 + br), zz1 = fsigmoid(xz1 + bz);
            float nn1 = ftanh_(fmaf(rr1, xn1 + bn, xi1 + bi));
            float v1 = fmaxf(fmaf(zz1, ho1 - nn1, nn1), 0.f);
            float w0 = __shfl_xor_sync(0xffffffffu, v0, 2);
            float w1 = __shfl_xor_sync(0xffffffffu, v1, 2);
            if (lk == 0) {
                if (rg0 < nrows) *(float2*)&g_hA[rg0 * 64 + j] = make_float2(v0, w0);
                if (rg1 < nrows) *(float2*)&g_hA[rg1 * 64 + j] = make_float2(v1, w1);
            }
        }
    }
}

// ============ attn_tail: vnW1 + hW2 + gate + s_g + s_h + BPR loss (4 sess/CTA)
// smem: sH bf16[80][72] | sW2 bf16[64][72] | sC f32[80][68] | sVn[4][64] |
//       sAl[80] | sSg[4][64] | sVnF[4][64] | sSh[4][64] | sW1 f32[64][65] | sW3 f32[64][129]
#define AT_SMEM (80*72*2 + 64*72*2 + 80*68*4 + 256*4 + 80*4 + 256*4 + 256*4 + 256*4 \
                 + 64*65*4 + 64*129*4)
__global__ void __launch_bounds__(256) attn_tail(
    const float* __restrict__ W1, const float* __restrict__ W3,
    const float* __restrict__ b1, const float* __restrict__ b2,
    const float* __restrict__ qw, const float* __restrict__ qb,
    const float* __restrict__ b3, const float* __restrict__ item_emb,
    const int* __restrict__ pos, const int* __restrict__ neg,
    int S, int L)
{
    extern __shared__ char smraw[];
    uint16_t* sH  = (uint16_t*)smraw;            // [80][72]
    uint16_t* sW2 = sH + 80 * 72;                // [64][72]
    float* sC  = (float*)(sW2 + 64 * 72);        // [80][68]
    float* sVn = sC + 80 * 68;                   // [4][64]
    float* sAl = sVn + 256;                      // [80]
    float* sSg = sAl + 80;                       // [4][64]
    float* sVnF= sSg + 256;                      // [4][64]
    float* sSh = sVnF + 256;                     // [4][64]
    float* sW1 = sSh + 256;                      // [64][65] pad-65 (conflict-free)
    float* sW3 = sW1 + 64 * 65;                  // [64][129] pad-129 (conflict-free)

    int tid = threadIdx.x, lane = tid & 31, warp = tid >> 5;
    int lr = lane >> 2, lk = lane & 3;
    int s0 = blockIdx.x * 4;
    int rowBase = s0 * L;

    // stage W1/W3 into padded smem (coalesced gmem reads)
    for (int i = tid; i < 64 * 64; i += 256)
        sW1[(i >> 6) * 65 + (i & 63)] = __ldg(&W1[i]);
    for (int i = tid; i < 64 * 128; i += 256)
        sW3[(i >> 7) * 129 + (i & 127)] = __ldg(&W3[i]);

    // fill sH (bf16 from g_hA) + sW2 async
    for (int i = tid; i < 80 * 8; i += 256) {
        int rl = i >> 3, seg = (i & 7) * 8;
        int gr = rowBase + rl;
        float4 v0 = *(const float4*)&g_hA[gr * 64 + seg];
        float4 v1 = *(const float4*)&g_hA[gr * 64 + seg + 4];
        uint32_t* dp = (uint32_t*)&sH[rl * 72 + seg];
        dp[0] = pbf2(v0.x, v0.y); dp[1] = pbf2(v0.z, v0.w);
        dp[2] = pbf2(v1.x, v1.y); dp[3] = pbf2(v1.z, v1.w);
    }
    for (int i = tid; i < 64 * 8; i += 256) {
        int c = i >> 3, q = (i & 7) * 8;
        cp16(smem_u32(&sW2[c * 72 + q]), &g_w2Bb[c * 64 + q]);
    }
    asm volatile("cp.async.commit_group;");
    asm volatile("cp.async.wait_group 0;");
    __syncthreads();

    // warps 0-4: hW2 mma -> sC fp32;  warps 5-7: vnW1 -> sVn (smem W1)
    if (warp < 5) {
        int r0 = warp * 16 + lr;
        float acc[8][4];
#pragma unroll
        for (int nt = 0; nt < 8; nt++)
#pragma unroll
            for (int q = 0; q < 4; q++) acc[nt][q] = 0.f;
#pragma unroll
        for (int k0 = 0; k0 < 64; k0 += 16) {
            uint32_t a[4];
            a[0] = *(const uint32_t*)&sH[r0 * 72 + k0 + 2 * lk];
            a[1] = *(const uint32_t*)&sH[(r0 + 8) * 72 + k0 + 2 * lk];
            a[2] = *(const uint32_t*)&sH[r0 * 72 + k0 + 8 + 2 * lk];
            a[3] = *(const uint32_t*)&sH[(r0 + 8) * 72 + k0 + 8 + 2 * lk];
#pragma unroll
            for (int nt = 0; nt < 8; nt++) {
                int c = nt * 8 + lr;
                uint32_t b0 = *(const uint32_t*)&sW2[c * 72 + k0 + 2 * lk];
                uint32_t b1 = *(const uint32_t*)&sW2[c * 72 + k0 + 8 + 2 * lk];
                mma_bf16(acc[nt], a, b0, b1);
            }
        }
#pragma unroll
        for (int nt = 0; nt < 8; nt++) {
            int c0 = nt * 8 + 2 * lk;
            *(float2*)&sC[r0 * 68 + c0]       = make_float2(acc[nt][0], acc[nt][1]);
            *(float2*)&sC[(r0 + 8) * 68 + c0] = make_float2(acc[nt][2], acc[nt][3]);
        }
    } else {
        for (int o = (warp - 5) * 32 + lane; o < 256; o += 96) {
            int sess = o >> 6, c = o & 63;
            const float* vp = &g_hA[(size_t)((s0 + sess) * L + L - 1) * 64];
            const float* wp = &sW1[c * 65];
            float acc = 0.f;
#pragma unroll 8
            for (int k = 0; k < 64; k++) acc = fmaf(vp[k], wp[k], acc);
            sVn[o] = acc;
        }
    }
    __syncthreads();

    // gate + alpha per row
    for (int r = warp; r < 80; r += 8) {
        int sess = r / L;
        int j0 = lane, j1 = lane + 32;
        float x0 = sC[r * 68 + j0] + sVn[sess * 64 + j0] + __ldg(&b1[j0]) + __ldg(&b2[j0]);
        float x1 = sC[r * 68 + j1] + sVn[sess * 64 + j1] + __ldg(&b1[j1]) + __ldg(&b2[j1]);
        float a = fmaf(fsigmoid(x0), __ldg(&qw[j0]), fsigmoid(x1) * __ldg(&qw[j1]));
#pragma unroll
        for (int o = 16; o; o >>= 1) a += __shfl_xor_sync(0xffffffffu, a, o);
        if (lane == 0) sAl[r] = a + __ldg(&qb[0]);
    }
    __syncthreads();

    // s_g (fp32, no atomics) + v_n fp32
    {
        int sess = tid >> 6, c = tid & 63;
        int gr0 = (s0 + sess) * L;
        float sg = 0.f;
        for (int i2 = 0; i2 < L; i2++)
            sg = fmaf(sAl[sess * L + i2], g_hA[(size_t)(gr0 + i2) * 64 + c], sg);
        sSg[tid] = sg;
        sVnF[tid] = g_hA[(size_t)(gr0 + L - 1) * 64 + c];
    }
    __syncthreads();

    // s_h = [vn | sg] @ W3^T + b3  (smem W3, conflict-free)
    {
        int sess = tid >> 6, c = tid & 63;
        const float* w3r = &sW3[c * 129];
        float acc = __ldg(&b3[c]);
#pragma unroll 8
        for (int k = 0; k < 64; k++) acc = fmaf(sVnF[sess * 64 + k], w3r[k], acc);
#pragma unroll 8
        for (int k = 0; k < 64; k++) acc = fmaf(sSg[sess * 64 + k], w3r[64 + k], acc);
        sSh[tid] = acc;
    }
    __syncthreads();

    // BPR loss (warp per session)
    if (warp < 4) {
        int gs = s0 + warp;
        if (gs < S) {
            int ip = __ldg(&pos[gs]), in2 = __ldg(&neg[gs]);
            float pp = 0.f, np = 0.f, rg = 0.f;
#pragma unroll
            for (int t = 0; t < 2; t++) {
                int j = lane + t * 32;
                float sv = sSh[warp * 64 + j];
                float pe = __ldg(&item_emb[(size_t)ip * 64 + j]);
                float ne = __ldg(&item_emb[(size_t)in2 * 64 + j]);
                pp = fmaf(sv, pe, pp);
                np = fmaf(sv, ne, np);
                rg += sv * sv + pe * pe + ne * ne;
            }
#pragma unroll
            for (int o = 16; o; o >>= 1) {
                pp += __shfl_xor_sync(0xffffffffu, pp, o);
                np += __shfl_xor_sync(0xffffffffu, np, o);
                rg += __shfl_xor_sync(0xffffffffu, rg, o);
            }
            if (lane == 0) {
                float x = pp - np;
                float lsm = (x > 0.f) ? log1pf(expf(-x)) : (-x + log1pf(expf(x)));
                atomicAdd(&g_acc[0], (double)lsm);
                atomicAdd(&g_acc[1], (double)rg);
            }
        }
    }
}

__global__ void finalize_kernel(float* out, int out_size)
{
    double loss = g_acc[0];
    double nr = g_acc[1] * 1e-5;
    float t = (float)(loss + nr), l = (float)loss, r = (float)nr;
    if (out_size > 0) out[0] = t;
    if (out_size > 1) out[1] = l;
    if (out_size > 2) out[2] = r;
    if (out_size > 3) out[3] = r;
    if (out_size > 4) out[4] = r;
}

// ---------------------------------------------------------------- host
extern "C" void kernel_launch(void* const* d_in, const int* in_sizes, int n_in,
                              void* d_out, int out_size)
{
    const float* item_emb = (const float*)d_in[0];
    const float* ggc      = (const float*)d_in[1];
    const float* W_ih     = (const float*)d_in[2];
    const float* b_ih     = (const float*)d_in[3];
    const float* W_hh     = (const float*)d_in[4];
    const float* b_hh     = (const float*)d_in[5];
    const float* W1       = (const float*)d_in[6];
    const float* b1       = (const float*)d_in[7];
    const float* W2       = (const float*)d_in[8];
    const float* b2       = (const float*)d_in[9];
    const float* qw       = (const float*)d_in[10];
    const float* qb       = (const float*)d_in[11];
    const float* W3       = (const float*)d_in[12];
    const float* b3       = (const float*)d_in[13];
    const int* node_items = (const int*)d_in[14];
    const int* edge_index = (const int*)d_in[15];
    const int* pos        = (const int*)d_in[17];
    const int* neg        = (const int*)d_in[18];

    int N = in_sizes[14];
    int E = in_sizes[15] / 2;
    int S = in_sizes[17];
    int L = N / S;                       // 20 for this problem instance
    float* out = (float*)d_out;

    cudaFuncSetAttribute(gnn2,      cudaFuncAttributeMaxDynamicSharedMemorySize, GNN_SMEM);
    cudaFuncSetAttribute(attn_tail, cudaFuncAttributeMaxDynamicSharedMemorySize, AT_SMEM);

    const int* src = edge_index;
    const int* dst = edge_index + E;

    init_all<<<(N + 255) / 256, 256>>>(W_ih, W_hh, ggc, W2, N);
    build_inedge_kernel<<<(E + 255) / 256, 256>>>(src, dst, E);

    gnn2<<<(N + 79) / 80, 256, GNN_SMEM>>>(b_ih, b_hh, N, item_emb, node_items);

    attn_tail<<<(S + 3) / 4, 256, AT_SMEM>>>(W1, W3, b1, b2, qw, qb, b3,
                                             item_emb, pos, neg, S, L);
    finalize_kernel<<<1, 1>>>(out, out_size);
}

// round 14
// speedup vs baseline: 2.1074x; 1.0039x over previous
#include <cuda_runtime.h>
#include <cuda_bf16.h>
#include <math.h>
#include <stdint.h>

#define D 64
#define N_MAX 327680
#define S_MAX 16384

// ---- scratch ----
__device__ float g_hA  [N_MAX * D];   // final h after both layers (+relu)
__device__ int   g_inedge[N_MAX];
__device__ double g_acc[2];
__device__ __align__(16) uint16_t g_gruBb[256 * 128];   // bf16 gate-interleaved [c=4j+g][k]
__device__ __align__(16) uint16_t g_msgGb[2 * 64 * 64]; // bf16 [layer][col j][k]
__device__ __align__(16) uint16_t g_w2Bb [64 * 64];     // bf16 [j][k]

// ---------------------------------------------------------------- helpers
__device__ __forceinline__ float fsigmoid(float x) {
    float e = __expf(-x);
    float r;
    asm("rcp.approx.f32 %0, %1;" : "=f"(r) : "f"(1.f + e));
    return r;
}
__device__ __forceinline__ float ftanh_(float x) {
    float t;
    asm("tanh.approx.f32 %0, %1;" : "=f"(t) : "f"(x));
    return t;
}
__device__ __forceinline__ uint32_t pbf2(float lo, float hi) {
    uint32_t o;
    asm("cvt.rn.bf16x2.f32 %0, %1, %2;" : "=r"(o) : "f"(hi), "f"(lo));
    return o;
}
__device__ __forceinline__ float bf2f(uint16_t u) {
    return __uint_as_float(((uint32_t)u) << 16);
}
__device__ __forceinline__ uint32_t smem_u32(const void* p) {
    return (uint32_t)__cvta_generic_to_shared(p);
}
__device__ __forceinline__ void cp16(uint32_t dst, const void* src) {
    asm volatile("cp.async.cg.shared.global [%0], [%1], 16;" :: "r"(dst), "l"(src));
}
__device__ __forceinline__ void mma_bf16(float d[4], const uint32_t a[4],
                                         uint32_t b0, uint32_t b1)
{
    asm volatile(
        "mma.sync.aligned.m16n8k16.row.col.f32.bf16.bf16.f32 "
        "{%0,%1,%2,%3}, {%4,%5,%6,%7}, {%8,%9}, {%0,%1,%2,%3};"
        : "+f"(d[0]), "+f"(d[1]), "+f"(d[2]), "+f"(d[3])
        : "r"(a[0]), "r"(a[1]), "r"(a[2]), "r"(a[3]), "r"(b0), "r"(b1));
}

// ------------------------------------- merged init: prepack + zero
__global__ void init_all(const float* __restrict__ W_ih, const float* __restrict__ W_hh,
                         const float* __restrict__ ggc, const float* __restrict__ W2,
                         int N)
{
    int i = blockIdx.x * blockDim.x + threadIdx.x;
    if (i < 256 * 128) {
        int c = i >> 7, k = i & 127;
        int j = c >> 2, g = c & 3;
        float v;
        if (g == 0)      v = (k < 64) ? W_ih[j * 64 + k]         : W_hh[j * 64 + (k - 64)];
        else if (g == 1) v = (k < 64) ? W_ih[(64 + j) * 64 + k]  : W_hh[(64 + j) * 64 + (k - 64)];
        else if (g == 2) v = (k < 64) ? W_ih[(128 + j) * 64 + k] : 0.f;
        else             v = (k < 64) ? 0.f                       : W_hh[(128 + j) * 64 + (k - 64)];
        g_gruBb[i] = __bfloat16_as_ushort(__float2bfloat16_rn(v));
    } else if (i < 256 * 128 + 2 * 4096) {
        int t = i - 256 * 128;
        int layer = t >> 12, r = t & 4095;
        int j = r >> 6, k = r & 63;
        g_msgGb[t] = __bfloat16_as_ushort(__float2bfloat16_rn(ggc[layer * 4096 + k * 64 + j]));
    } else if (i < 256 * 128 + 2 * 4096 + 4096) {
        int t = i - (256 * 128 + 2 * 4096);
        g_w2Bb[t] = __bfloat16_as_ushort(__float2bfloat16_rn(W2[t]));
    }
    if (i < 2) g_acc[i] = 0.0;
    if (i < N) g_inedge[i] = -1;
}
__global__ void build_inedge_kernel(const int* __restrict__ src,
                                    const int* __restrict__ dst, int E)
{
    int e = blockIdx.x * blockDim.x + threadIdx.x;
    if (e < E) g_inedge[dst[e]] = src[e];
}

// ============== single-kernel 2-layer GGC+GRU (80-row session-aligned tiles)
#define XP 72
#define BKP 136
#define OF_X0  5760
#define OF_X1  11520
#define OF_G   17280
#define OF_B   21888
#define GNN_SMEM ((21888 + 256 * 136) * 2)

__device__ __forceinline__ void p1_tile(uint16_t* sSrc, uint16_t* sDst,
                                        const uint16_t* sG, int rb, int lr, int lk)
{
    int r0 = rb * 16 + lr;
    float p[8][4];
#pragma unroll
    for (int nt = 0; nt < 8; nt++)
#pragma unroll
        for (int q = 0; q < 4; q++) p[nt][q] = 0.f;
#pragma unroll
    for (int k0 = 0; k0 < 64; k0 += 16) {
        uint32_t a[4];
        a[0] = *(const uint32_t*)&sSrc[r0 * XP + k0 + 2 * lk];
        a[1] = *(const uint32_t*)&sSrc[(r0 + 8) * XP + k0 + 2 * lk];
        a[2] = *(const uint32_t*)&sSrc[r0 * XP + k0 + 8 + 2 * lk];
        a[3] = *(const uint32_t*)&sSrc[(r0 + 8) * XP + k0 + 8 + 2 * lk];
#pragma unroll
        for (int nt = 0; nt < 8; nt++) {
            int c = nt * 8 + lr;
            uint32_t b0 = *(const uint32_t*)&sG[c * XP + k0 + 2 * lk];
            uint32_t b1 = *(const uint32_t*)&sG[c * XP + k0 + 8 + 2 * lk];
            mma_bf16(p[nt], a, b0, b1);
        }
    }
#pragma unroll
    for (int nt = 0; nt < 8; nt++) {
        int c0 = nt * 8 + 2 * lk;
        *(uint32_t*)&sDst[r0 * XP + c0]       = pbf2(p[nt][0], p[nt][1]);
        *(uint32_t*)&sDst[(r0 + 8) * XP + c0] = pbf2(p[nt][2], p[nt][3]);
    }
}

__global__ void __launch_bounds__(256, 2) gnn2(
    const float* __restrict__ b_ih, const float* __restrict__ b_hh,
    int nrows, const float* __restrict__ emb, const int* __restrict__ items)
{
    extern __shared__ uint16_t sm[];
    uint16_t* sAgg = sm;
    uint16_t* sX0  = sm + OF_X0;
    uint16_t* sX1  = sm + OF_X1;
    uint16_t* sG   = sm + OF_G;
    uint16_t* sB   = sm + OF_B;

    int tid = threadIdx.x, lane = tid & 31, warp = tid >> 5;
    int lr = lane >> 2, lk = lane & 3;
    int rowBase = blockIdx.x * 80;

    for (int i = tid; i < 64 * 8; i += 256) {
        int c = i >> 3, q = (i & 7) * 8;
        cp16(smem_u32(&sG[c * XP + q]), &g_msgGb[c * 64 + q]);
    }
    asm volatile("cp.async.commit_group;");
    for (int i = tid; i < 256 * 16; i += 256) {
        int c = i >> 4, q = (i & 15) * 8;
        cp16(smem_u32(&sB[c * BKP + q]), &g_gruBb[c * 128 + q]);
    }
    asm volatile("cp.async.commit_group;");

    for (int i = tid; i < 80 * 8; i += 256) {
        int rl = i >> 3, seg = (i & 7) * 8;
        int gr = rowBase + rl;
        float4 v0 = make_float4(0.f,0.f,0.f,0.f), v1 = v0;
        if (gr < nrows) {
            const float* sp = emb + (size_t)(__ldg(&items[gr]) - 1) * 64;
            v0 = *(const float4*)&sp[seg];
            v1 = *(const float4*)&sp[seg + 4];
        }
        uint32_t* dp = (uint32_t*)&sX0[rl * XP + seg];
        dp[0] = pbf2(v0.x, v0.y); dp[1] = pbf2(v0.z, v0.w);
        dp[2] = pbf2(v1.x, v1.y); dp[3] = pbf2(v1.z, v1.w);
    }
    __syncthreads();

    for (int i = tid; i < 80 * 8; i += 256) {
        int rl = i >> 3, q = (i & 7) * 8;
        int gr = rowBase + rl;
        int p = (gr < nrows) ? __ldg(&g_inedge[gr]) : -1;
        uint4 z = make_uint4(0u, 0u, 0u, 0u);
        uint4 v = (p >= 0 && rl > 0) ? *(const uint4*)&sX0[(rl - 1) * XP + q] : z;
        *(uint4*)&sAgg[rl * XP + q] = v;
    }
    asm volatile("cp.async.wait_group 1;");
    __syncthreads();

    if (warp < 5) p1_tile(sAgg, sAgg, sG, warp, lr, lk);
    asm volatile("cp.async.wait_group 0;");
    __syncthreads();

    // layer 0 phase 2 + GRU epilogue -> sX1
    for (int t = warp; t < 20; t += 8) {
        int rb = t >> 2, cb = t & 3;
        int r0 = rb * 16 + lr;
        int colW = cb * 64;
        float acc[8][4];
#pragma unroll
        for (int nt = 0; nt < 8; nt++)
#pragma unroll
            for (int q = 0; q < 4; q++) acc[nt][q] = 0.f;
#pragma unroll
        for (int kk = 0; kk < 8; kk++) {
            int k0 = kk * 16;
            const uint16_t* ab = (k0 < 64) ? sAgg : sX0;
            int kc = (k0 < 64) ? k0 : k0 - 64;
            uint32_t a[4];
            a[0] = *(const uint32_t*)&ab[r0 * XP + kc + 2 * lk];
            a[1] = *(const uint32_t*)&ab[(r0 + 8) * XP + kc + 2 * lk];
            a[2] = *(const uint32_t*)&ab[r0 * XP + kc + 8 + 2 * lk];
            a[3] = *(const uint32_t*)&ab[(r0 + 8) * XP + kc + 8 + 2 * lk];
#pragma unroll
            for (int nt = 0; nt < 8; nt++) {
                int c = colW + nt * 8 + lr;
                uint32_t b0 = *(const uint32_t*)&sB[c * BKP + k0 + 2 * lk];
                uint32_t b1 = *(const uint32_t*)&sB[c * BKP + k0 + 8 + 2 * lk];
                mma_bf16(acc[nt], a, b0, b1);
            }
        }
        int base_j = colW >> 2;
        int odd = lk & 1;
        int rg0 = rowBase + r0, rg1 = rg0 + 8;
        const float* hop0 = (rg0 < nrows) ? emb + (size_t)(__ldg(&items[rg0]) - 1) * 64 : nullptr;
        const float* hop1 = (rg1 < nrows) ? emb + (size_t)(__ldg(&items[rg1]) - 1) * 64 : nullptr;
#pragma unroll
        for (int nt = 0; nt < 8; nt++) {
            int j = base_j + 2 * nt + ((lk >> 1) & 1);
            float s0 = acc[nt][0], s1 = acc[nt][1], s2 = acc[nt][2], s3 = acc[nt][3];
            float e0 = __shfl_xor_sync(0xffffffffu, s0, 1);
            float e1 = __shfl_xor_sync(0xffffffffu, s1, 1);
            float e2 = __shfl_xor_sync(0xffffffffu, s2, 1);
            float e3 = __shfl_xor_sync(0xffffffffu, s3, 1);
            float xr0 = odd ? e0 : s0, xz0 = odd ? e1 : s1;
            float xi0 = odd ? s0 : e0, xn0 = odd ? s1 : e1;
            float xr1 = odd ? e2 : s2, xz1 = odd ? e3 : s3;
            float xi1 = odd ? s2 : e2, xn1 = odd ? s3 : e3;
            float br = __ldg(&b_ih[j])      + __ldg(&b_hh[j]);
            float bz = __ldg(&b_ih[64 + j]) + __ldg(&b_hh[64 + j]);
            float bi = __ldg(&b_ih[128 + j]);
            float bn = __ldg(&b_hh[128 + j]);
            float ho0 = hop0 ? hop0[j] : 0.f;
            float ho1 = hop1 ? hop1[j] : 0.f;
            float rr0 = fsigmoid(xr0 + br), zz0 = fsigmoid(xz0 + bz);
            float nn0 = ftanh_(fmaf(rr0, xn0 + bn, xi0 + bi));
            float v0 = fmaf(zz0, ho0 - nn0, nn0);
            float rr1 = fsigmoid(xr1 + br), zz1 = fsigmoid(xz1 + bz);
            float nn1 = ftanh_(fmaf(rr1, xn1 + bn, xi1 + bi));
            float v1 = fmaf(zz1, ho1 - nn1, nn1);
            float w0 = __shfl_xor_sync(0xffffffffu, v0, 2);
            float w1 = __shfl_xor_sync(0xffffffffu, v1, 2);
            if (lk == 0) {
                *(uint32_t*)&sX1[r0 * XP + j]       = pbf2(v0, w0);
                *(uint32_t*)&sX1[(r0 + 8) * XP + j] = pbf2(v1, w1);
            }
        }
    }
    __syncthreads();

    for (int i = tid; i < 64 * 8; i += 256) {
        int c = i >> 3, q = (i & 7) * 8;
        cp16(smem_u32(&sG[c * XP + q]), &g_msgGb[4096 + c * 64 + q]);
    }
    asm volatile("cp.async.commit_group;");
    for (int i = tid; i < 80 * 8; i += 256) {
        int rl = i >> 3, q = (i & 7) * 8;
        int gr = rowBase + rl;
        int p = (gr < nrows) ? __ldg(&g_inedge[gr]) : -1;
        uint4 z = make_uint4(0u, 0u, 0u, 0u);
        uint4 v = (p >= 0 && rl > 0) ? *(const uint4*)&sX1[(rl - 1) * XP + q] : z;
        *(uint4*)&sAgg[rl * XP + q] = v;
    }
    asm volatile("cp.async.wait_group 0;");
    __syncthreads();

    if (warp < 5) p1_tile(sAgg, sAgg, sG, warp, lr, lk);
    __syncthreads();

    // layer 1 phase 2 + GRU epilogue (+relu) -> g_hA
    for (int t = warp; t < 20; t += 8) {
        int rb = t >> 2, cb = t & 3;
        int r0 = rb * 16 + lr;
        int colW = cb * 64;
        float acc[8][4];
#pragma unroll
        for (int nt = 0; nt < 8; nt++)
#pragma unroll
            for (int q = 0; q < 4; q++) acc[nt][q] = 0.f;
#pragma unroll
        for (int kk = 0; kk < 8; kk++) {
            int k0 = kk * 16;
            const uint16_t* ab = (k0 < 64) ? sAgg : sX1;
            int kc = (k0 < 64) ? k0 : k0 - 64;
            uint32_t a[4];
            a[0] = *(const uint32_t*)&ab[r0 * XP + kc + 2 * lk];
            a[1] = *(const uint32_t*)&ab[(r0 + 8) * XP + kc + 2 * lk];
            a[2] = *(const uint32_t*)&ab[r0 * XP + kc + 8 + 2 * lk];
            a[3] = *(const uint32_t*)&ab[(r0 + 8) * XP + kc + 8 + 2 * lk];
#pragma unroll
            for (int nt = 0; nt < 8; nt++) {
                int c = colW + nt * 8 + lr;
                uint32_t b0 = *(const uint32_t*)&sB[c * BKP + k0 + 2 * lk];
                uint32_t b1 = *(const uint32_t*)&sB[c * BKP + k0 + 8 + 2 * lk];
                mma_bf16(acc[nt], a, b0, b1);
            }
        }
        int base_j = colW >> 2;
        int odd = lk & 1;
        int rg0 = rowBase + r0, rg1 = rg0 + 8;
#pragma unroll
        for (int nt = 0; nt < 8; nt++) {
            int j = base_j + 2 * nt + ((lk >> 1) & 1);
            float s0 = acc[nt][0], s1 = acc[nt][1], s2 = acc[nt][2], s3 = acc[nt][3];
            float e0 = __shfl_xor_sync(0xffffffffu, s0, 1);
            float e1 = __shfl_xor_sync(0xffffffffu, s1, 1);
            float e2 = __shfl_xor_sync(0xffffffffu, s2, 1);
            float e3 = __shfl_xor_sync(0xffffffffu, s3, 1);
            float xr0 = odd ? e0 : s0, xz0 = odd ? e1 : s1;
            float xi0 = odd ? s0 : e0, xn0 = odd ? s1 : e1;
            float xr1 = odd ? e2 : s2, xz1 = odd ? e3 : s3;
            float xi1 = odd ? s2 : e2, xn1 = odd ? s3 : e3;
            float br = __ldg(&b_ih[j])      + __ldg(&b_hh[j]);
            float bz = __ldg(&b_ih[64 + j]) + __ldg(&b_hh[64 + j]);
            float bi = __ldg(&b_ih[128 + j]);
            float bn = __ldg(&b_hh[128 + j]);
            float ho0 = bf2f(sX1[r0 * XP + j]);
            float ho1 = bf2f(sX1[(r0 + 8) * XP + j]);
            float rr0 = fsigmoid(xr0 + br), zz0 = fsigmoid(xz0 + bz);
            float nn0 = ftanh_(fmaf(rr0, xn0 + bn, xi0 + bi));
            float v0 = fmaxf(fmaf(zz0, ho0 - nn0, nn0), 0.f);
            float rr1 = fsigmoid(xr1 + br), zz1 = fsigmoid(xz1 + bz);
            float nn1 = ftanh_(fmaf(rr1, xn1 + bn, xi1 + bi));
            float v1 = fmaxf(fmaf(zz1, ho1 - nn1, nn1), 0.f);
            float w0 = __shfl_xor_sync(0xffffffffu, v0, 2);
            float w1 = __shfl_xor_sync(0xffffffffu, v1, 2);
            if (lk == 0) {
                if (rg0 < nrows) *(float2*)&g_hA[rg0 * 64 + j] = make_float2(v0, w0);
                if (rg1 < nrows) *(float2*)&g_hA[rg1 * 64 + j] = make_float2(v1, w1);
            }
        }
    }
}

// ============ attn_tail: vnW1 + hW2 + gate + s_g + s_h + BPR loss (4 sess/CTA)
// smem: sH bf16[80][72] | sW2 bf16[64][72] | sC f32[80][68] | sVn[4][64] |
//       sAl[80] | sSg[4][64] | sVnF[4][64] | sSh[4][64] | sW1 f32[64][65] | sW3 f32[64][129]
#define AT_SMEM (80*72*2 + 64*72*2 + 80*68*4 + 256*4 + 80*4 + 256*4 + 256*4 + 256*4 \
                 + 64*65*4 + 64*129*4)
__global__ void __launch_bounds__(256) attn_tail(
    const float* __restrict__ W1, const float* __restrict__ W3,
    const float* __restrict__ b1, const float* __restrict__ b2,
    const float* __restrict__ qw, const float* __restrict__ qb,
    const float* __restrict__ b3, const float* __restrict__ item_emb,
    const int* __restrict__ pos, const int* __restrict__ neg,
    int S, int L)
{
    extern __shared__ char smraw[];
    uint16_t* sH  = (uint16_t*)smraw;            // [80][72]
    uint16_t* sW2 = sH + 80 * 72;                // [64][72]
    float* sC  = (float*)(sW2 + 64 * 72);        // [80][68]
    float* sVn = sC + 80 * 68;                   // [4][64]
    float* sAl = sVn + 256;                      // [80]
    float* sSg = sAl + 80;                       // [4][64]
    float* sVnF= sSg + 256;                      // [4][64]
    float* sSh = sVnF + 256;                     // [4][64]
    float* sW1 = sSh + 256;                      // [64][65] pad-65 (conflict-free)
    float* sW3 = sW1 + 64 * 65;                  // [64][129] pad-129 (conflict-free)

    int tid = threadIdx.x, lane = tid & 31, warp = tid >> 5;
    int lr = lane >> 2, lk = lane & 3;
    int s0 = blockIdx.x * 4;
    int rowBase = s0 * L;

    // stage W1/W3 into padded smem (coalesced gmem reads)
    for (int i = tid; i < 64 * 64; i += 256)
        sW1[(i >> 6) * 65 + (i & 63)] = __ldg(&W1[i]);
    for (int i = tid; i < 64 * 128; i += 256)
        sW3[(i >> 7) * 129 + (i & 127)] = __ldg(&W3[i]);

    // fill sH (bf16 from g_hA) + sW2 async
    for (int i = tid; i < 80 * 8; i += 256) {
        int rl = i >> 3, seg = (i & 7) * 8;
        int gr = rowBase + rl;
        float4 v0 = *(const float4*)&g_hA[gr * 64 + seg];
        float4 v1 = *(const float4*)&g_hA[gr * 64 + seg + 4];
        uint32_t* dp = (uint32_t*)&sH[rl * 72 + seg];
        dp[0] = pbf2(v0.x, v0.y); dp[1] = pbf2(v0.z, v0.w);
        dp[2] = pbf2(v1.x, v1.y); dp[3] = pbf2(v1.z, v1.w);
    }
    for (int i = tid; i < 64 * 8; i += 256) {
        int c = i >> 3, q = (i & 7) * 8;
        cp16(smem_u32(&sW2[c * 72 + q]), &g_w2Bb[c * 64 + q]);
    }
    asm volatile("cp.async.commit_group;");
    asm volatile("cp.async.wait_group 0;");
    __syncthreads();

    // warps 0-4: hW2 mma -> sC fp32;  warps 5-7: vnW1 -> sVn (smem W1)
    if (warp < 5) {
        int r0 = warp * 16 + lr;
        float acc[8][4];
#pragma unroll
        for (int nt = 0; nt < 8; nt++)
#pragma unroll
            for (int q = 0; q < 4; q++) acc[nt][q] = 0.f;
#pragma unroll
        for (int k0 = 0; k0 < 64; k0 += 16) {
            uint32_t a[4];
            a[0] = *(const uint32_t*)&sH[r0 * 72 + k0 + 2 * lk];
            a[1] = *(const uint32_t*)&sH[(r0 + 8) * 72 + k0 + 2 * lk];
            a[2] = *(const uint32_t*)&sH[r0 * 72 + k0 + 8 + 2 * lk];
            a[3] = *(const uint32_t*)&sH[(r0 + 8) * 72 + k0 + 8 + 2 * lk];
#pragma unroll
            for (int nt = 0; nt < 8; nt++) {
                int c = nt * 8 + lr;
                uint32_t b0 = *(const uint32_t*)&sW2[c * 72 + k0 + 2 * lk];
                uint32_t b1 = *(const uint32_t*)&sW2[c * 72 + k0 + 8 + 2 * lk];
                mma_bf16(acc[nt], a, b0, b1);
            }
        }
#pragma unroll
        for (int nt = 0; nt < 8; nt++) {
            int c0 = nt * 8 + 2 * lk;
            *(float2*)&sC[r0 * 68 + c0]       = make_float2(acc[nt][0], acc[nt][1]);
            *(float2*)&sC[(r0 + 8) * 68 + c0] = make_float2(acc[nt][2], acc[nt][3]);
        }
    } else {
        for (int o = (warp - 5) * 32 + lane; o < 256; o += 96) {
            int sess = o >> 6, c = o & 63;
            const float* vp = &g_hA[(size_t)((s0 + sess) * L + L - 1) * 64];
            const float* wp = &sW1[c * 65];
            float acc = 0.f;
#pragma unroll 8
            for (int k = 0; k < 64; k++) acc = fmaf(vp[k], wp[k], acc);
            sVn[o] = acc;
        }
    }
    __syncthreads();

    // gate + alpha per row
    for (int r = warp; r < 80; r += 8) {
        int sess = r / L;
        int j0 = lane, j1 = lane + 32;
        float x0 = sC[r * 68 + j0] + sVn[sess * 64 + j0] + __ldg(&b1[j0]) + __ldg(&b2[j0]);
        float x1 = sC[r * 68 + j1] + sVn[sess * 64 + j1] + __ldg(&b1[j1]) + __ldg(&b2[j1]);
        float a = fmaf(fsigmoid(x0), __ldg(&qw[j0]), fsigmoid(x1) * __ldg(&qw[j1]));
#pragma unroll
        for (int o = 16; o; o >>= 1) a += __shfl_xor_sync(0xffffffffu, a, o);
        if (lane == 0) sAl[r] = a + __ldg(&qb[0]);
    }
    __syncthreads();

    // s_g (fp32, no atomics) + v_n fp32
    {
        int sess = tid >> 6, c = tid & 63;
        int gr0 = (s0 + sess) * L;
        float sg = 0.f;
        for (int i2 = 0; i2 < L; i2++)
            sg = fmaf(sAl[sess * L + i2], g_hA[(size_t)(gr0 + i2) * 64 + c], sg);
        sSg[tid] = sg;
        sVnF[tid] = g_hA[(size_t)(gr0 + L - 1) * 64 + c];
    }
    __syncthreads();

    // s_h = [vn | sg] @ W3^T + b3  (smem W3, conflict-free)
    {
        int sess = tid >> 6, c = tid & 63;
        const float* w3r = &sW3[c * 129];
        float acc = __ldg(&b3[c]);
#pragma unroll 8
        for (int k = 0; k < 64; k++) acc = fmaf(sVnF[sess * 64 + k], w3r[k], acc);
#pragma unroll 8
        for (int k = 0; k < 64; k++) acc = fmaf(sSg[sess * 64 + k], w3r[64 + k], acc);
        sSh[tid] = acc;
    }
    __syncthreads();

    // BPR loss (warp per session)
    if (warp < 4) {
        int gs = s0 + warp;
        if (gs < S) {
            int ip = __ldg(&pos[gs]), in2 = __ldg(&neg[gs]);
            float pp = 0.f, np = 0.f, rg = 0.f;
#pragma unroll
            for (int t = 0; t < 2; t++) {
                int j = lane + t * 32;
                float sv = sSh[warp * 64 + j];
                float pe = __ldg(&item_emb[(size_t)ip * 64 + j]);
                float ne = __ldg(&item_emb[(size_t)in2 * 64 + j]);
                pp = fmaf(sv, pe, pp);
                np = fmaf(sv, ne, np);
                rg += sv * sv + pe * pe + ne * ne;
            }
#pragma unroll
            for (int o = 16; o; o >>= 1) {
                pp += __shfl_xor_sync(0xffffffffu, pp, o);
                np += __shfl_xor_sync(0xffffffffu, np, o);
                rg += __shfl_xor_sync(0xffffffffu, rg, o);
            }
            if (lane == 0) {
                float x = pp - np;
                float lsm = (x > 0.f) ? log1pf(expf(-x)) : (-x + log1pf(expf(x)));
                atomicAdd(&g_acc[0], (double)lsm);
                atomicAdd(&g_acc[1], (double)rg);
            }
        }
    }
}

__global__ void finalize_kernel(float* out, int out_size)
{
    double loss = g_acc[0];
    double nr = g_acc[1] * 1e-5;
    float t = (float)(loss + nr), l = (float)loss, r = (float)nr;
    if (out_size > 0) out[0] = t;
    if (out_size > 1) out[1] = l;
    if (out_size > 2) out[2] = r;
    if (out_size > 3) out[3] = r;
    if (out_size > 4) out[4] = r;
}

// ---------------------------------------------------------------- host
extern "C" void kernel_launch(void* const* d_in, const int* in_sizes, int n_in,
                              void* d_out, int out_size)
{
    const float* item_emb = (const float*)d_in[0];
    const float* ggc      = (const float*)d_in[1];
    const float* W_ih     = (const float*)d_in[2];
    const float* b_ih     = (const float*)d_in[3];
    const float* W_hh     = (const float*)d_in[4];
    const float* b_hh     = (const float*)d_in[5];
    const float* W1       = (const float*)d_in[6];
    const float* b1       = (const float*)d_in[7];
    const float* W2       = (const float*)d_in[8];
    const float* b2       = (const float*)d_in[9];
    const float* qw       = (const float*)d_in[10];
    const float* qb       = (const float*)d_in[11];
    const float* W3       = (const float*)d_in[12];
    const float* b3       = (const float*)d_in[13];
    const int* node_items = (const int*)d_in[14];
    const int* edge_index = (const int*)d_in[15];
    const int* pos        = (const int*)d_in[17];
    const int* neg        = (const int*)d_in[18];

    int N = in_sizes[14];
    int E = in_sizes[15] / 2;
    int S = in_sizes[17];
    int L = N / S;                       // 20 for this problem instance
    float* out = (float*)d_out;

    cudaFuncSetAttribute(gnn2,      cudaFuncAttributeMaxDynamicSharedMemorySize, GNN_SMEM);
    cudaFuncSetAttribute(attn_tail, cudaFuncAttributeMaxDynamicSharedMemorySize, AT_SMEM);

    const int* src = edge_index;
    const int* dst = edge_index + E;

    init_all<<<(N + 255) / 256, 256>>>(W_ih, W_hh, ggc, W2, N);
    build_inedge_kernel<<<(E + 255) / 256, 256>>>(src, dst, E);

    gnn2<<<(N + 79) / 80, 256, GNN_SMEM>>>(b_ih, b_hh, N, item_emb, node_items);

    attn_tail<<<(S + 3) / 4, 256, AT_SMEM>>>(W1, W3, b1, b2, qw, qb, b3,
                                             item_emb, pos, neg, S, L);
    finalize_kernel<<<1, 1>>>(out, out_size);
}

// round 15
// speedup vs baseline: 2.4505x; 1.1628x over previous
#include <cuda_runtime.h>
#include <cuda_bf16.h>
#include <math.h>
#include <stdint.h>

#define D 64
#define N_MAX 327680
#define S_MAX 16384

// ---- scratch ----
__device__ float g_hA  [N_MAX * D];   // final h after both layers (+relu)
__device__ int   g_inedge[N_MAX];
__device__ double g_acc[2];
__device__ __align__(16) uint16_t g_gruBb[256 * 128];   // bf16 gate-interleaved [c=4j+g][k]
__device__ __align__(16) uint16_t g_msgGb[2 * 64 * 64]; // bf16 [layer][col j][k]
__device__ __align__(16) uint16_t g_w2Bb [64 * 64];     // bf16 [j][k]

// ---------------------------------------------------------------- helpers
__device__ __forceinline__ float fsigmoid(float x) {
    float e = __expf(-x);
    float r;
    asm("rcp.approx.f32 %0, %1;" : "=f"(r) : "f"(1.f + e));
    return r;
}
__device__ __forceinline__ float ftanh_(float x) {
    float t;
    asm("tanh.approx.f32 %0, %1;" : "=f"(t) : "f"(x));
    return t;
}
__device__ __forceinline__ uint32_t pbf2(float lo, float hi) {
    uint32_t o;
    asm("cvt.rn.bf16x2.f32 %0, %1, %2;" : "=r"(o) : "f"(hi), "f"(lo));
    return o;
}
__device__ __forceinline__ float bf2f(uint16_t u) {
    return __uint_as_float(((uint32_t)u) << 16);
}
__device__ __forceinline__ uint32_t smem_u32(const void* p) {
    return (uint32_t)__cvta_generic_to_shared(p);
}
__device__ __forceinline__ void cp16(uint32_t dst, const void* src) {
    asm volatile("cp.async.cg.shared.global [%0], [%1], 16;" :: "r"(dst), "l"(src));
}
__device__ __forceinline__ void mma_bf16(float d[4], const uint32_t a[4],
                                         uint32_t b0, uint32_t b1)
{
    asm volatile(
        "mma.sync.aligned.m16n8k16.row.col.f32.bf16.bf16.f32 "
        "{%0,%1,%2,%3}, {%4,%5,%6,%7}, {%8,%9}, {%0,%1,%2,%3};"
        : "+f"(d[0]), "+f"(d[1]), "+f"(d[2]), "+f"(d[3])
        : "r"(a[0]), "r"(a[1]), "r"(a[2]), "r"(a[3]), "r"(b0), "r"(b1));
}

// ------------------------------------- merged init: prepack + zero
__global__ void init_all(const float* __restrict__ W_ih, const float* __restrict__ W_hh,
                         const float* __restrict__ ggc, const float* __restrict__ W2,
                         int N)
{
    int i = blockIdx.x * blockDim.x + threadIdx.x;
    if (i < 256 * 128) {
        int c = i >> 7, k = i & 127;
        int j = c >> 2, g = c & 3;
        float v;
        if (g == 0)      v = (k < 64) ? W_ih[j * 64 + k]         : W_hh[j * 64 + (k - 64)];
        else if (g == 1) v = (k < 64) ? W_ih[(64 + j) * 64 + k]  : W_hh[(64 + j) * 64 + (k - 64)];
        else if (g == 2) v = (k < 64) ? W_ih[(128 + j) * 64 + k] : 0.f;
        else             v = (k < 64) ? 0.f                       : W_hh[(128 + j) * 64 + (k - 64)];
        g_gruBb[i] = __bfloat16_as_ushort(__float2bfloat16_rn(v));
    } else if (i < 256 * 128 + 2 * 4096) {
        int t = i - 256 * 128;
        int layer = t >> 12, r = t & 4095;
        int j = r >> 6, k = r & 63;
        g_msgGb[t] = __bfloat16_as_ushort(__float2bfloat16_rn(ggc[layer * 4096 + k * 64 + j]));
    } else if (i < 256 * 128 + 2 * 4096 + 4096) {
        int t = i - (256 * 128 + 2 * 4096);
        g_w2Bb[t] = __bfloat16_as_ushort(__float2bfloat16_rn(W2[t]));
    }
    if (i < 2) g_acc[i] = 0.0;
    if (i < N) g_inedge[i] = -1;
}
__global__ void build_inedge_kernel(const int* __restrict__ src,
                                    const int* __restrict__ dst, int E)
{
    int e = blockIdx.x * blockDim.x + threadIdx.x;
    if (e < E) g_inedge[dst[e]] = src[e];
}

// ============== single-kernel 2-layer GGC+GRU (80-row session-aligned tiles)
#define XP 72
#define BKP 136
#define OF_X0  5760
#define OF_X1  11520
#define OF_G   17280
#define OF_B   21888
#define GNN_SMEM ((21888 + 256 * 136) * 2)

__device__ __forceinline__ void p1_tile(uint16_t* sSrc, uint16_t* sDst,
                                        const uint16_t* sG, int rb, int lr, int lk)
{
    int r0 = rb * 16 + lr;
    float p[8][4];
#pragma unroll
    for (int nt = 0; nt < 8; nt++)
#pragma unroll
        for (int q = 0; q < 4; q++) p[nt][q] = 0.f;
#pragma unroll
    for (int k0 = 0; k0 < 64; k0 += 16) {
        uint32_t a[4];
        a[0] = *(const uint32_t*)&sSrc[r0 * XP + k0 + 2 * lk];
        a[1] = *(const uint32_t*)&sSrc[(r0 + 8) * XP + k0 + 2 * lk];
        a[2] = *(const uint32_t*)&sSrc[r0 * XP + k0 + 8 + 2 * lk];
        a[3] = *(const uint32_t*)&sSrc[(r0 + 8) * XP + k0 + 8 + 2 * lk];
#pragma unroll
        for (int nt = 0; nt < 8; nt++) {
            int c = nt * 8 + lr;
            uint32_t b0 = *(const uint32_t*)&sG[c * XP + k0 + 2 * lk];
            uint32_t b1 = *(const uint32_t*)&sG[c * XP + k0 + 8 + 2 * lk];
            mma_bf16(p[nt], a, b0, b1);
        }
    }
#pragma unroll
    for (int nt = 0; nt < 8; nt++) {
        int c0 = nt * 8 + 2 * lk;
        *(uint32_t*)&sDst[r0 * XP + c0]       = pbf2(p[nt][0], p[nt][1]);
        *(uint32_t*)&sDst[(r0 + 8) * XP + c0] = pbf2(p[nt][2], p[nt][3]);
    }
}

__global__ void __launch_bounds__(256, 2) gnn2(
    const float* __restrict__ b_ih, const float* __restrict__ b_hh,
    int nrows, const float* __restrict__ emb, const int* __restrict__ items)
{
    extern __shared__ uint16_t sm[];
    uint16_t* sAgg = sm;
    uint16_t* sX0  = sm + OF_X0;
    uint16_t* sX1  = sm + OF_X1;
    uint16_t* sG   = sm + OF_G;
    uint16_t* sB   = sm + OF_B;

    int tid = threadIdx.x, lane = tid & 31, warp = tid >> 5;
    int lr = lane >> 2, lk = lane & 3;
    int rowBase = blockIdx.x * 80;

    for (int i = tid; i < 64 * 8; i += 256) {
        int c = i >> 3, q = (i & 7) * 8;
        cp16(smem_u32(&sG[c * XP + q]), &g_msgGb[c * 64 + q]);
    }
    asm volatile("cp.async.commit_group;");
    for (int i = tid; i < 256 * 16; i += 256) {
        int c = i >> 4, q = (i & 15) * 8;
        cp16(smem_u32(&sB[c * BKP + q]), &g_gruBb[c * 128 + q]);
    }
    asm volatile("cp.async.commit_group;");

    for (int i = tid; i < 80 * 8; i += 256) {
        int rl = i >> 3, seg = (i & 7) * 8;
        int gr = rowBase + rl;
        float4 v0 = make_float4(0.f,0.f,0.f,0.f), v1 = v0;
        if (gr < nrows) {
            const float* sp = emb + (size_t)(__ldg(&items[gr]) - 1) * 64;
            v0 = *(const float4*)&sp[seg];
            v1 = *(const float4*)&sp[seg + 4];
        }
        uint32_t* dp = (uint32_t*)&sX0[rl * XP + seg];
        dp[0] = pbf2(v0.x, v0.y); dp[1] = pbf2(v0.z, v0.w);
        dp[2] = pbf2(v1.x, v1.y); dp[3] = pbf2(v1.z, v1.w);
    }
    __syncthreads();

    for (int i = tid; i < 80 * 8; i += 256) {
        int rl = i >> 3, q = (i & 7) * 8;
        int gr = rowBase + rl;
        int p = (gr < nrows) ? __ldg(&g_inedge[gr]) : -1;
        uint4 z = make_uint4(0u, 0u, 0u, 0u);
        uint4 v = (p >= 0 && rl > 0) ? *(const uint4*)&sX0[(rl - 1) * XP + q] : z;
        *(uint4*)&sAgg[rl * XP + q] = v;
    }
    asm volatile("cp.async.wait_group 1;");
    __syncthreads();

    if (warp < 5) p1_tile(sAgg, sAgg, sG, warp, lr, lk);
    asm volatile("cp.async.wait_group 0;");
    __syncthreads();

    // layer 0 phase 2 + GRU epilogue -> sX1
    for (int t = warp; t < 20; t += 8) {
        int rb = t >> 2, cb = t & 3;
        int r0 = rb * 16 + lr;
        int colW = cb * 64;
        float acc[8][4];
#pragma unroll
        for (int nt = 0; nt < 8; nt++)
#pragma unroll
            for (int q = 0; q < 4; q++) acc[nt][q] = 0.f;
#pragma unroll
        for (int kk = 0; kk < 8; kk++) {
            int k0 = kk * 16;
            const uint16_t* ab = (k0 < 64) ? sAgg : sX0;
            int kc = (k0 < 64) ? k0 : k0 - 64;
            uint32_t a[4];
            a[0] = *(const uint32_t*)&ab[r0 * XP + kc + 2 * lk];
            a[1] = *(const uint32_t*)&ab[(r0 + 8) * XP + kc + 2 * lk];
            a[2] = *(const uint32_t*)&ab[r0 * XP + kc + 8 + 2 * lk];
            a[3] = *(const uint32_t*)&ab[(r0 + 8) * XP + kc + 8 + 2 * lk];
#pragma unroll
            for (int nt = 0; nt < 8; nt++) {
                int c = colW + nt * 8 + lr;
                uint32_t b0 = *(const uint32_t*)&sB[c * BKP + k0 + 2 * lk];
                uint32_t b1 = *(const uint32_t*)&sB[c * BKP + k0 + 8 + 2 * lk];
                mma_bf16(acc[nt], a, b0, b1);
            }
        }
        int base_j = colW >> 2;
        int odd = lk & 1;
        int rg0 = rowBase + r0, rg1 = rg0 + 8;
        const float* hop0 = (rg0 < nrows) ? emb + (size_t)(__ldg(&items[rg0]) - 1) * 64 : nullptr;
        const float* hop1 = (rg1 < nrows) ? emb + (size_t)(__ldg(&items[rg1]) - 1) * 64 : nullptr;
#pragma unroll
        for (int nt = 0; nt < 8; nt++) {
            int j = base_j + 2 * nt + ((lk >> 1) & 1);
            float s0 = acc[nt][0], s1 = acc[nt][1], s2 = acc[nt][2], s3 = acc[nt][3];
            float e0 = __shfl_xor_sync(0xffffffffu, s0, 1);
            float e1 = __shfl_xor_sync(0xffffffffu, s1, 1);
            float e2 = __shfl_xor_sync(0xffffffffu, s2, 1);
            float e3 = __shfl_xor_sync(0xffffffffu, s3, 1);
            float xr0 = odd ? e0 : s0, xz0 = odd ? e1 : s1;
            float xi0 = odd ? s0 : e0, xn0 = odd ? s1 : e1;
            float xr1 = odd ? e2 : s2, xz1 = odd ? e3 : s3;
            float xi1 = odd ? s2 : e2, xn1 = odd ? s3 : e3;
            float br = __ldg(&b_ih[j])      + __ldg(&b_hh[j]);
            float bz = __ldg(&b_ih[64 + j]) + __ldg(&b_hh[64 + j]);
            float bi = __ldg(&b_ih[128 + j]);
            float bn = __ldg(&b_hh[128 + j]);
            float ho0 = hop0 ? hop0[j] : 0.f;
            float ho1 = hop1 ? hop1[j] : 0.f;
            float rr0 = fsigmoid(xr0 + br), zz0 = fsigmoid(xz0 + bz);
            float nn0 = ftanh_(fmaf(rr0, xn0 + bn, xi0 + bi));
            float v0 = fmaf(zz0, ho0 - nn0, nn0);
            float rr1 = fsigmoid(xr1 + br), zz1 = fsigmoid(xz1 + bz);
            float nn1 = ftanh_(fmaf(rr1, xn1 + bn, xi1 + bi));
            float v1 = fmaf(zz1, ho1 - nn1, nn1);
            float w0 = __shfl_xor_sync(0xffffffffu, v0, 2);
            float w1 = __shfl_xor_sync(0xffffffffu, v1, 2);
            if (lk == 0) {
                *(uint32_t*)&sX1[r0 * XP + j]       = pbf2(v0, w0);
                *(uint32_t*)&sX1[(r0 + 8) * XP + j] = pbf2(v1, w1);
            }
        }
    }
    __syncthreads();

    for (int i = tid; i < 64 * 8; i += 256) {
        int c = i >> 3, q = (i & 7) * 8;
        cp16(smem_u32(&sG[c * XP + q]), &g_msgGb[4096 + c * 64 + q]);
    }
    asm volatile("cp.async.commit_group;");
    for (int i = tid; i < 80 * 8; i += 256) {
        int rl = i >> 3, q = (i & 7) * 8;
        int gr = rowBase + rl;
        int p = (gr < nrows) ? __ldg(&g_inedge[gr]) : -1;
        uint4 z = make_uint4(0u, 0u, 0u, 0u);
        uint4 v = (p >= 0 && rl > 0) ? *(const uint4*)&sX1[(rl - 1) * XP + q] : z;
        *(uint4*)&sAgg[rl * XP + q] = v;
    }
    asm volatile("cp.async.wait_group 0;");
    __syncthreads();

    if (warp < 5) p1_tile(sAgg, sAgg, sG, warp, lr, lk);
    __syncthreads();

    // layer 1 phase 2 + GRU epilogue (+relu) -> g_hA
    for (int t = warp; t < 20; t += 8) {
        int rb = t >> 2, cb = t & 3;
        int r0 = rb * 16 + lr;
        int colW = cb * 64;
        float acc[8][4];
#pragma unroll
        for (int nt = 0; nt < 8; nt++)
#pragma unroll
            for (int q = 0; q < 4; q++) acc[nt][q] = 0.f;
#pragma unroll
        for (int kk = 0; kk < 8; kk++) {
            int k0 = kk * 16;
            const uint16_t* ab = (k0 < 64) ? sAgg : sX1;
            int kc = (k0 < 64) ? k0 : k0 - 64;
            uint32_t a[4];
            a[0] = *(const uint32_t*)&ab[r0 * XP + kc + 2 * lk];
            a[1] = *(const uint32_t*)&ab[(r0 + 8) * XP + kc + 2 * lk];
            a[2] = *(const uint32_t*)&ab[r0 * XP + kc + 8 + 2 * lk];
            a[3] = *(const uint32_t*)&ab[(r0 + 8) * XP + kc + 8 + 2 * lk];
#pragma unroll
            for (int nt = 0; nt < 8; nt++) {
                int c = colW + nt * 8 + lr;
                uint32_t b0 = *(const uint32_t*)&sB[c * BKP + k0 + 2 * lk];
                uint32_t b1 = *(const uint32_t*)&sB[c * BKP + k0 + 8 + 2 * lk];
                mma_bf16(acc[nt], a, b0, b1);
            }
        }
        int base_j = colW >> 2;
        int odd = lk & 1;
        int rg0 = rowBase + r0, rg1 = rg0 + 8;
#pragma unroll
        for (int nt = 0; nt < 8; nt++) {
            int j = base_j + 2 * nt + ((lk >> 1) & 1);
            float s0 = acc[nt][0], s1 = acc[nt][1], s2 = acc[nt][2], s3 = acc[nt][3];
            float e0 = __shfl_xor_sync(0xffffffffu, s0, 1);
            float e1 = __shfl_xor_sync(0xffffffffu, s1, 1);
            float e2 = __shfl_xor_sync(0xffffffffu, s2, 1);
            float e3 = __shfl_xor_sync(0xffffffffu, s3, 1);
            float xr0 = odd ? e0 : s0, xz0 = odd ? e1 : s1;
            float xi0 = odd ? s0 : e0, xn0 = odd ? s1 : e1;
            float xr1 = odd ? e2 : s2, xz1 = odd ? e3 : s3;
            float xi1 = odd ? s2 : e2, xn1 = odd ? s3 : e3;
            float br = __ldg(&b_ih[j])      + __ldg(&b_hh[j]);
            float bz = __ldg(&b_ih[64 + j]) + __ldg(&b_hh[64 + j]);
            float bi = __ldg(&b_ih[128 + j]);
            float bn = __ldg(&b_hh[128 + j]);
            float ho0 = bf2f(sX1[r0 * XP + j]);
            float ho1 = bf2f(sX1[(r0 + 8) * XP + j]);
            float rr0 = fsigmoid(xr0 + br), zz0 = fsigmoid(xz0 + bz);
            float nn0 = ftanh_(fmaf(rr0, xn0 + bn, xi0 + bi));
            float v0 = fmaxf(fmaf(zz0, ho0 - nn0, nn0), 0.f);
            float rr1 = fsigmoid(xr1 + br), zz1 = fsigmoid(xz1 + bz);
            float nn1 = ftanh_(fmaf(rr1, xn1 + bn, xi1 + bi));
            float v1 = fmaxf(fmaf(zz1, ho1 - nn1, nn1), 0.f);
            float w0 = __shfl_xor_sync(0xffffffffu, v0, 2);
            float w1 = __shfl_xor_sync(0xffffffffu, v1, 2);
            if (lk == 0) {
                if (rg0 < nrows) *(float2*)&g_hA[rg0 * 64 + j] = make_float2(v0, w0);
                if (rg1 < nrows) *(float2*)&g_hA[rg1 * 64 + j] = make_float2(v1, w1);
            }
        }
    }
}

// ============ attn_tail v2: bf16 weights, register gate, 4 sess/CTA, 52.8 KB
// smem: sH bf16[80][72] | sW2 bf16[64][72] | sW1t bf16[64][72](trans) |
//       sW3t bf16[128][72](trans) | sVn f32[256] | sAl f32[80] |
//       sSg f32[256] | sVnF f32[256] | sSh f32[256]
#define AT_SMEM (80*72*2 + 64*72*2 + 64*72*2 + 128*72*2 + 256*4 + 80*4 + 3*256*4)
__global__ void __launch_bounds__(256) attn_tail(
    const float* __restrict__ W1, const float* __restrict__ W3,
    const float* __restrict__ b1, const float* __restrict__ b2,
    const float* __restrict__ qw, const float* __restrict__ qb,
    const float* __restrict__ b3, const float* __restrict__ item_emb,
    const int* __restrict__ pos, const int* __restrict__ neg,
    int S, int L, int nrows)
{
    extern __shared__ char smraw[];
    uint16_t* sH   = (uint16_t*)smraw;           // [80][72]
    uint16_t* sW2  = sH + 80 * 72;               // [64][72]
    uint16_t* sW1t = sW2 + 64 * 72;              // [64][72]: sW1t[k*72+c] = W1[c][k]
    uint16_t* sW3t = sW1t + 64 * 72;             // [128][72]: sW3t[k*72+c] = W3[c][k]
    float* sVn  = (float*)(sW3t + 128 * 72);     // [4][64]
    float* sAl  = sVn + 256;                     // [80]
    float* sSg  = sAl + 80;                      // [4][64]
    float* sVnF = sSg + 256;                     // [4][64]
    float* sSh  = sVnF + 256;                    // [4][64]

    int tid = threadIdx.x, lane = tid & 31, warp = tid >> 5;
    int lr = lane >> 2, lk = lane & 3;
    int s0 = blockIdx.x * 4;
    int rowBase = s0 * L;

    // sW2 async
    for (int i = tid; i < 64 * 8; i += 256) {
        int c = i >> 3, q = (i & 7) * 8;
        cp16(smem_u32(&sW2[c * 72 + q]), &g_w2Bb[c * 64 + q]);
    }
    asm volatile("cp.async.commit_group;");
    // sH (bf16 from g_hA)
    for (int i = tid; i < 80 * 8; i += 256) {
        int rl = i >> 3, seg = (i & 7) * 8;
        int gr = rowBase + rl;
        float4 v0 = make_float4(0.f,0.f,0.f,0.f), v1 = v0;
        if (gr < nrows) {
            v0 = *(const float4*)&g_hA[gr * 64 + seg];
            v1 = *(const float4*)&g_hA[gr * 64 + seg + 4];
        }
        uint32_t* dp = (uint32_t*)&sH[rl * 72 + seg];
        dp[0] = pbf2(v0.x, v0.y); dp[1] = pbf2(v0.z, v0.w);
        dp[2] = pbf2(v1.x, v1.y); dp[3] = pbf2(v1.z, v1.w);
    }
    // transposed bf16 W1/W3 (coalesced gmem reads, strided smem writes)
    for (int i = tid; i < 64 * 64; i += 256) {
        int c = i >> 6, k = i & 63;
        sW1t[k * 72 + c] = __bfloat16_as_ushort(__float2bfloat16_rn(__ldg(&W1[i])));
    }
    for (int i = tid; i < 64 * 128; i += 256) {
        int c = i >> 7, k = i & 127;
        sW3t[k * 72 + c] = __bfloat16_as_ushort(__float2bfloat16_rn(__ldg(&W3[i])));
    }
    asm volatile("cp.async.wait_group 0;");
    __syncthreads();

    // sVn: one output per thread (sess = tid>>6, c = tid&63)
    {
        int sess = tid >> 6, c = tid & 63;
        int row = sess * L + L - 1;
        float acc = 0.f;
#pragma unroll 8
        for (int k = 0; k < 64; k++)
            acc = fmaf(bf2f(sH[row * 72 + k]), bf2f(sW1t[k * 72 + c]), acc);
        sVn[tid] = acc;
    }
    __syncthreads();

    // warps 0-4: hW2 mma (16 rows each) + register gate epilogue -> sAl
    if (warp < 5) {
        int r0 = warp * 16 + lr;
        float acc[8][4];
#pragma unroll
        for (int nt = 0; nt < 8; nt++)
#pragma unroll
            for (int q = 0; q < 4; q++) acc[nt][q] = 0.f;
#pragma unroll
        for (int k0 = 0; k0 < 64; k0 += 16) {
            uint32_t a[4];
            a[0] = *(const uint32_t*)&sH[r0 * 72 + k0 + 2 * lk];
            a[1] = *(const uint32_t*)&sH[(r0 + 8) * 72 + k0 + 2 * lk];
            a[2] = *(const uint32_t*)&sH[r0 * 72 + k0 + 8 + 2 * lk];
            a[3] = *(const uint32_t*)&sH[(r0 + 8) * 72 + k0 + 8 + 2 * lk];
#pragma unroll
            for (int nt = 0; nt < 8; nt++) {
                int c = nt * 8 + lr;
                uint32_t b0 = *(const uint32_t*)&sW2[c * 72 + k0 + 2 * lk];
                uint32_t b1 = *(const uint32_t*)&sW2[c * 72 + k0 + 8 + 2 * lk];
                mma_bf16(acc[nt], a, b0, b1);
            }
        }
        int ra = warp * 16 + lr, rb2 = ra + 8;
        int sa = ra / L, sb = rb2 / L;
        float al0 = 0.f, al1 = 0.f;
#pragma unroll
        for (int nt = 0; nt < 8; nt++) {
#pragma unroll
            for (int q = 0; q < 2; q++) {
                int c = nt * 8 + 2 * lk + q;
                float bb = __ldg(&b1[c]) + __ldg(&b2[c]);
                float qv = __ldg(&qw[c]);
                float x0 = acc[nt][q]     + sVn[sa * 64 + c] + bb;
                float x1 = acc[nt][2 + q] + sVn[sb * 64 + c] + bb;
                al0 = fmaf(fsigmoid(x0), qv, al0);
                al1 = fmaf(fsigmoid(x1), qv, al1);
            }
        }
        al0 += __shfl_xor_sync(0xffffffffu, al0, 1);
        al0 += __shfl_xor_sync(0xffffffffu, al0, 2);
        al1 += __shfl_xor_sync(0xffffffffu, al1, 1);
        al1 += __shfl_xor_sync(0xffffffffu, al1, 2);
        float qbv = __ldg(&qb[0]);
        if (lk == 0) { sAl[ra] = al0 + qbv; sAl[rb2] = al1 + qbv; }
    }
    __syncthreads();

    // s_g from bf16 sH (conflict-free) + exact fp32 v_n from gmem
    {
        int sess = tid >> 6, c = tid & 63;
        int rl0 = sess * L;
        float sg = 0.f;
        for (int i2 = 0; i2 < L; i2++)
            sg = fmaf(sAl[rl0 + i2], bf2f(sH[(rl0 + i2) * 72 + c]), sg);
        sSg[tid] = sg;
        int gvn = rowBase + rl0 + L - 1;
        sVnF[tid] = (gvn < nrows) ? g_hA[(size_t)gvn * 64 + c] : 0.f;
    }
    __syncthreads();

    // s_h = [vn | sg] @ W3^T + b3  (bf16 transposed W3, broadcast-friendly)
    {
        int sess = tid >> 6, c = tid & 63;
        float acc = __ldg(&b3[c]);
#pragma unroll 8
        for (int k = 0; k < 64; k++)
            acc = fmaf(sVnF[sess * 64 + k], bf2f(sW3t[k * 72 + c]), acc);
#pragma unroll 8
        for (int k = 0; k < 64; k++)
            acc = fmaf(sSg[sess * 64 + k], bf2f(sW3t[(64 + k) * 72 + c]), acc);
        sSh[tid] = acc;
    }
    __syncthreads();

    // BPR loss (warp per session)
    if (warp < 4) {
        int gs = s0 + warp;
        if (gs < S) {
            int ip = __ldg(&pos[gs]), in2 = __ldg(&neg[gs]);
            float pp = 0.f, np = 0.f, rg = 0.f;
#pragma unroll
            for (int t = 0; t < 2; t++) {
                int j = lane + t * 32;
                float sv = sSh[warp * 64 + j];
                float pe = __ldg(&item_emb[(size_t)ip * 64 + j]);
                float ne = __ldg(&item_emb[(size_t)in2 * 64 + j]);
                pp = fmaf(sv, pe, pp);
                np = fmaf(sv, ne, np);
                rg += sv * sv + pe * pe + ne * ne;
            }
#pragma unroll
            for (int o = 16; o; o >>= 1) {
                pp += __shfl_xor_sync(0xffffffffu, pp, o);
                np += __shfl_xor_sync(0xffffffffu, np, o);
                rg += __shfl_xor_sync(0xffffffffu, rg, o);
            }
            if (lane == 0) {
                float x = pp - np;
                float lsm = (x > 0.f) ? log1pf(expf(-x)) : (-x + log1pf(expf(x)));
                atomicAdd(&g_acc[0], (double)lsm);
                atomicAdd(&g_acc[1], (double)rg);
            }
        }
    }
}

__global__ void finalize_kernel(float* out, int out_size)
{
    double loss = g_acc[0];
    double nr = g_acc[1] * 1e-5;
    float t = (float)(loss + nr), l = (float)loss, r = (float)nr;
    if (out_size > 0) out[0] = t;
    if (out_size > 1) out[1] = l;
    if (out_size > 2) out[2] = r;
    if (out_size > 3) out[3] = r;
    if (out_size > 4) out[4] = r;
}

// ---------------------------------------------------------------- host
extern "C" void kernel_launch(void* const* d_in, const int* in_sizes, int n_in,
                              void* d_out, int out_size)
{
    const float* item_emb = (const float*)d_in[0];
    const float* ggc      = (const float*)d_in[1];
    const float* W_ih     = (const float*)d_in[2];
    const float* b_ih     = (const float*)d_in[3];
    const float* W_hh     = (const float*)d_in[4];
    const float* b_hh     = (const float*)d_in[5];
    const float* W1       = (const float*)d_in[6];
    const float* b1       = (const float*)d_in[7];
    const float* W2       = (const float*)d_in[8];
    const float* b2       = (const float*)d_in[9];
    const float* qw       = (const float*)d_in[10];
    const float* qb       = (const float*)d_in[11];
    const float* W3       = (const float*)d_in[12];
    const float* b3       = (const float*)d_in[13];
    const int* node_items = (const int*)d_in[14];
    const int* edge_index = (const int*)d_in[15];
    const int* pos        = (const int*)d_in[17];
    const int* neg        = (const int*)d_in[18];

    int N = in_sizes[14];
    int E = in_sizes[15] / 2;
    int S = in_sizes[17];
    int L = N / S;                       // 20 for this problem instance
    float* out = (float*)d_out;

    cudaFuncSetAttribute(gnn2,      cudaFuncAttributeMaxDynamicSharedMemorySize, GNN_SMEM);
    cudaFuncSetAttribute(attn_tail, cudaFuncAttributeMaxDynamicSharedMemorySize, AT_SMEM);

    const int* src = edge_index;
    const int* dst = edge_index + E;

    init_all<<<(N + 255) / 256, 256>>>(W_ih, W_hh, ggc, W2, N);
    build_inedge_kernel<<<(E + 255) / 256, 256>>>(src, dst, E);

    gnn2<<<(N + 79) / 80, 256, GNN_SMEM>>>(b_ih, b_hh, N, item_emb, node_items);

    attn_tail<<<(S + 3) / 4, 256, AT_SMEM>>>(W1, W3, b1, b2, qw, qb, b3,
                                             item_emb, pos, neg, S, L, N);
    finalize_kernel<<<1, 1>>>(out, out_size);
}

// round 16
// speedup vs baseline: 2.7364x; 1.1167x over previous
#include <cuda_runtime.h>
#include <cuda_bf16.h>
#include <math.h>
#include <stdint.h>

#define D 64
#define N_MAX 327680
#define S_MAX 16384

// ---- scratch ----
__device__ float g_hA  [N_MAX * D];   // final h after both layers (+relu)
__device__ int   g_inedge[N_MAX];
__device__ double g_acc[2];
__device__ __align__(16) uint16_t g_gruBb[256 * 128];   // bf16 gate-interleaved [c=4j+g][k]
__device__ __align__(16) uint16_t g_msgGb[2 * 64 * 64]; // bf16 [layer][col j][k]
__device__ __align__(16) uint16_t g_w2Bb [64 * 64];     // bf16 [j][k]

// ---------------------------------------------------------------- helpers
__device__ __forceinline__ float fsigmoid(float x) {
    float e = __expf(-x);
    float r;
    asm("rcp.approx.f32 %0, %1;" : "=f"(r) : "f"(1.f + e));
    return r;
}
__device__ __forceinline__ float ftanh_(float x) {
    float t;
    asm("tanh.approx.f32 %0, %1;" : "=f"(t) : "f"(x));
    return t;
}
__device__ __forceinline__ uint32_t pbf2(float lo, float hi) {
    uint32_t o;
    asm("cvt.rn.bf16x2.f32 %0, %1, %2;" : "=r"(o) : "f"(hi), "f"(lo));
    return o;
}
__device__ __forceinline__ float bf2f(uint16_t u) {
    return __uint_as_float(((uint32_t)u) << 16);
}
__device__ __forceinline__ uint32_t smem_u32(const void* p) {
    return (uint32_t)__cvta_generic_to_shared(p);
}
__device__ __forceinline__ void cp16(uint32_t dst, const void* src) {
    asm volatile("cp.async.cg.shared.global [%0], [%1], 16;" :: "r"(dst), "l"(src));
}
__device__ __forceinline__ void mma_bf16(float d[4], const uint32_t a[4],
                                         uint32_t b0, uint32_t b1)
{
    asm volatile(
        "mma.sync.aligned.m16n8k16.row.col.f32.bf16.bf16.f32 "
        "{%0,%1,%2,%3}, {%4,%5,%6,%7}, {%8,%9}, {%0,%1,%2,%3};"
        : "+f"(d[0]), "+f"(d[1]), "+f"(d[2]), "+f"(d[3])
        : "r"(a[0]), "r"(a[1]), "r"(a[2]), "r"(a[3]), "r"(b0), "r"(b1));
}

// ------------------------------------- merged init: prepack + zero
__global__ void init_all(const float* __restrict__ W_ih, const float* __restrict__ W_hh,
                         const float* __restrict__ ggc, const float* __restrict__ W2,
                         int N)
{
    int i = blockIdx.x * blockDim.x + threadIdx.x;
    if (i < 256 * 128) {
        int c = i >> 7, k = i & 127;
        int j = c >> 2, g = c & 3;
        float v;
        if (g == 0)      v = (k < 64) ? W_ih[j * 64 + k]         : W_hh[j * 64 + (k - 64)];
        else if (g == 1) v = (k < 64) ? W_ih[(64 + j) * 64 + k]  : W_hh[(64 + j) * 64 + (k - 64)];
        else if (g == 2) v = (k < 64) ? W_ih[(128 + j) * 64 + k] : 0.f;
        else             v = (k < 64) ? 0.f                       : W_hh[(128 + j) * 64 + (k - 64)];
        g_gruBb[i] = __bfloat16_as_ushort(__float2bfloat16_rn(v));
    } else if (i < 256 * 128 + 2 * 4096) {
        int t = i - 256 * 128;
        int layer = t >> 12, r = t & 4095;
        int j = r >> 6, k = r & 63;
        g_msgGb[t] = __bfloat16_as_ushort(__float2bfloat16_rn(ggc[layer * 4096 + k * 64 + j]));
    } else if (i < 256 * 128 + 2 * 4096 + 4096) {
        int t = i - (256 * 128 + 2 * 4096);
        g_w2Bb[t] = __bfloat16_as_ushort(__float2bfloat16_rn(W2[t]));
    }
    if (i < 2) g_acc[i] = 0.0;
    if (i < N) g_inedge[i] = -1;
}
__global__ void build_inedge_kernel(const int* __restrict__ src,
                                    const int* __restrict__ dst, int E)
{
    int e = blockIdx.x * blockDim.x + threadIdx.x;
    if (e < E) g_inedge[dst[e]] = src[e];
}

// ============== single-kernel 2-layer GGC+GRU (80-row session-aligned tiles)
#define XP 72
#define BKP 136
#define OF_X0  5760
#define OF_X1  11520
#define OF_G   17280
#define OF_B   21888
#define GNN_SMEM ((21888 + 256 * 136) * 2)

__device__ __forceinline__ void p1_tile(uint16_t* sSrc, uint16_t* sDst,
                                        const uint16_t* sG, int rb, int lr, int lk)
{
    int r0 = rb * 16 + lr;
    float p[8][4];
#pragma unroll
    for (int nt = 0; nt < 8; nt++)
#pragma unroll
        for (int q = 0; q < 4; q++) p[nt][q] = 0.f;
#pragma unroll
    for (int k0 = 0; k0 < 64; k0 += 16) {
        uint32_t a[4];
        a[0] = *(const uint32_t*)&sSrc[r0 * XP + k0 + 2 * lk];
        a[1] = *(const uint32_t*)&sSrc[(r0 + 8) * XP + k0 + 2 * lk];
        a[2] = *(const uint32_t*)&sSrc[r0 * XP + k0 + 8 + 2 * lk];
        a[3] = *(const uint32_t*)&sSrc[(r0 + 8) * XP + k0 + 8 + 2 * lk];
#pragma unroll
        for (int nt = 0; nt < 8; nt++) {
            int c = nt * 8 + lr;
            uint32_t b0 = *(const uint32_t*)&sG[c * XP + k0 + 2 * lk];
            uint32_t b1 = *(const uint32_t*)&sG[c * XP + k0 + 8 + 2 * lk];
            mma_bf16(p[nt], a, b0, b1);
        }
    }
#pragma unroll
    for (int nt = 0; nt < 8; nt++) {
        int c0 = nt * 8 + 2 * lk;
        *(uint32_t*)&sDst[r0 * XP + c0]       = pbf2(p[nt][0], p[nt][1]);
        *(uint32_t*)&sDst[(r0 + 8) * XP + c0] = pbf2(p[nt][2], p[nt][3]);
    }
}

// phase-2 + GRU epilogue for one layer: 40 balanced 16x32 tiles (5 per warp)
// hOldSrc: smem bf16 [80][XP] holding h_old; out==nullptr -> write bf16 to sOut
__device__ __forceinline__ void p2_layer(
    const uint16_t* sAgg, const uint16_t* sXin, const uint16_t* sB,
    const uint16_t* sHold, uint16_t* sOut, float* gOut,
    const float* b_ih, const float* b_hh,
    int rowBase, int nrows, int do_relu, int warp, int lr, int lk)
{
    for (int t = warp; t < 40; t += 8) {
        int rb = t >> 3, cb = t & 7;
        int r0 = rb * 16 + lr;
        int colW = cb * 32;
        float acc[4][4];
#pragma unroll
        for (int nt = 0; nt < 4; nt++)
#pragma unroll
            for (int q = 0; q < 4; q++) acc[nt][q] = 0.f;
#pragma unroll
        for (int kk = 0; kk < 8; kk++) {
            int k0 = kk * 16;
            const uint16_t* ab = (k0 < 64) ? sAgg : sXin;
            int kc = (k0 < 64) ? k0 : k0 - 64;
            uint32_t a[4];
            a[0] = *(const uint32_t*)&ab[r0 * XP + kc + 2 * lk];
            a[1] = *(const uint32_t*)&ab[(r0 + 8) * XP + kc + 2 * lk];
            a[2] = *(const uint32_t*)&ab[r0 * XP + kc + 8 + 2 * lk];
            a[3] = *(const uint32_t*)&ab[(r0 + 8) * XP + kc + 8 + 2 * lk];
#pragma unroll
            for (int nt = 0; nt < 4; nt++) {
                int c = colW + nt * 8 + lr;
                uint32_t b0 = *(const uint32_t*)&sB[c * BKP + k0 + 2 * lk];
                uint32_t b1 = *(const uint32_t*)&sB[c * BKP + k0 + 8 + 2 * lk];
                mma_bf16(acc[nt], a, b0, b1);
            }
        }
        int base_j = colW >> 2;
        int odd = lk & 1;
        int rg0 = rowBase + r0, rg1 = rg0 + 8;
#pragma unroll
        for (int nt = 0; nt < 4; nt++) {
            int j = base_j + 2 * nt + ((lk >> 1) & 1);
            float s0 = acc[nt][0], s1 = acc[nt][1], s2 = acc[nt][2], s3 = acc[nt][3];
            float e0 = __shfl_xor_sync(0xffffffffu, s0, 1);
            float e1 = __shfl_xor_sync(0xffffffffu, s1, 1);
            float e2 = __shfl_xor_sync(0xffffffffu, s2, 1);
            float e3 = __shfl_xor_sync(0xffffffffu, s3, 1);
            float xr0 = odd ? e0 : s0, xz0 = odd ? e1 : s1;
            float xi0 = odd ? s0 : e0, xn0 = odd ? s1 : e1;
            float xr1 = odd ? e2 : s2, xz1 = odd ? e3 : s3;
            float xi1 = odd ? s2 : e2, xn1 = odd ? s3 : e3;
            float br = __ldg(&b_ih[j])      + __ldg(&b_hh[j]);
            float bz = __ldg(&b_ih[64 + j]) + __ldg(&b_hh[64 + j]);
            float bi = __ldg(&b_ih[128 + j]);
            float bn = __ldg(&b_hh[128 + j]);
            float ho0 = bf2f(sHold[r0 * XP + j]);
            float ho1 = bf2f(sHold[(r0 + 8) * XP + j]);
            float rr0 = fsigmoid(xr0 + br), zz0 = fsigmoid(xz0 + bz);
            float nn0 = ftanh_(fmaf(rr0, xn0 + bn, xi0 + bi));
            float v0 = fmaf(zz0, ho0 - nn0, nn0);
            float rr1 = fsigmoid(xr1 + br), zz1 = fsigmoid(xz1 + bz);
            float nn1 = ftanh_(fmaf(rr1, xn1 + bn, xi1 + bi));
            float v1 = fmaf(zz1, ho1 - nn1, nn1);
            if (do_relu) { v0 = fmaxf(v0, 0.f); v1 = fmaxf(v1, 0.f); }
            float w0 = __shfl_xor_sync(0xffffffffu, v0, 2);
            float w1 = __shfl_xor_sync(0xffffffffu, v1, 2);
            if (lk == 0) {
                if (gOut) {
                    if (rg0 < nrows) *(float2*)&gOut[rg0 * 64 + j] = make_float2(v0, w0);
                    if (rg1 < nrows) *(float2*)&gOut[rg1 * 64 + j] = make_float2(v1, w1);
                } else {
                    *(uint32_t*)&sOut[r0 * XP + j]       = pbf2(v0, w0);
                    *(uint32_t*)&sOut[(r0 + 8) * XP + j] = pbf2(v1, w1);
                }
            }
        }
    }
}

__global__ void __launch_bounds__(256, 2) gnn2(
    const float* __restrict__ b_ih, const float* __restrict__ b_hh,
    int nrows, const float* __restrict__ emb, const int* __restrict__ items)
{
    extern __shared__ uint16_t sm[];
    uint16_t* sAgg = sm;
    uint16_t* sX0  = sm + OF_X0;
    uint16_t* sX1  = sm + OF_X1;
    uint16_t* sG   = sm + OF_G;
    uint16_t* sB   = sm + OF_B;

    int tid = threadIdx.x, lane = tid & 31, warp = tid >> 5;
    int lr = lane >> 2, lk = lane & 3;
    int rowBase = blockIdx.x * 80;

    for (int i = tid; i < 64 * 8; i += 256) {
        int c = i >> 3, q = (i & 7) * 8;
        cp16(smem_u32(&sG[c * XP + q]), &g_msgGb[c * 64 + q]);
    }
    asm volatile("cp.async.commit_group;");
    for (int i = tid; i < 256 * 16; i += 256) {
        int c = i >> 4, q = (i & 15) * 8;
        cp16(smem_u32(&sB[c * BKP + q]), &g_gruBb[c * 128 + q]);
    }
    asm volatile("cp.async.commit_group;");

    for (int i = tid; i < 80 * 8; i += 256) {
        int rl = i >> 3, seg = (i & 7) * 8;
        int gr = rowBase + rl;
        float4 v0 = make_float4(0.f,0.f,0.f,0.f), v1 = v0;
        if (gr < nrows) {
            const float* sp = emb + (size_t)(__ldg(&items[gr]) - 1) * 64;
            v0 = *(const float4*)&sp[seg];
            v1 = *(const float4*)&sp[seg + 4];
        }
        uint32_t* dp = (uint32_t*)&sX0[rl * XP + seg];
        dp[0] = pbf2(v0.x, v0.y); dp[1] = pbf2(v0.z, v0.w);
        dp[2] = pbf2(v1.x, v1.y); dp[3] = pbf2(v1.z, v1.w);
    }
    __syncthreads();

    for (int i = tid; i < 80 * 8; i += 256) {
        int rl = i >> 3, q = (i & 7) * 8;
        int gr = rowBase + rl;
        int p = (gr < nrows) ? __ldg(&g_inedge[gr]) : -1;
        uint4 z = make_uint4(0u, 0u, 0u, 0u);
        uint4 v = (p >= 0 && rl > 0) ? *(const uint4*)&sX0[(rl - 1) * XP + q] : z;
        *(uint4*)&sAgg[rl * XP + q] = v;
    }
    asm volatile("cp.async.wait_group 1;");
    __syncthreads();

    if (warp < 5) p1_tile(sAgg, sAgg, sG, warp, lr, lk);
    asm volatile("cp.async.wait_group 0;");
    __syncthreads();

    // layer 0 phase 2 + epilogue (h_old from sX0 bf16) -> sX1
    p2_layer(sAgg, sX0, sB, sX0, sX1, nullptr,
             b_ih, b_hh, rowBase, nrows, 0, warp, lr, lk);
    __syncthreads();

    for (int i = tid; i < 64 * 8; i += 256) {
        int c = i >> 3, q = (i & 7) * 8;
        cp16(smem_u32(&sG[c * XP + q]), &g_msgGb[4096 + c * 64 + q]);
    }
    asm volatile("cp.async.commit_group;");
    for (int i = tid; i < 80 * 8; i += 256) {
        int rl = i >> 3, q = (i & 7) * 8;
        int gr = rowBase + rl;
        int p = (gr < nrows) ? __ldg(&g_inedge[gr]) : -1;
        uint4 z = make_uint4(0u, 0u, 0u, 0u);
        uint4 v = (p >= 0 && rl > 0) ? *(const uint4*)&sX1[(rl - 1) * XP + q] : z;
        *(uint4*)&sAgg[rl * XP + q] = v;
    }
    asm volatile("cp.async.wait_group 0;");
    __syncthreads();

    if (warp < 5) p1_tile(sAgg, sAgg, sG, warp, lr, lk);
    __syncthreads();

    // layer 1 phase 2 + epilogue (+relu, h_old from sX1) -> g_hA
    p2_layer(sAgg, sX1, sB, sX1, nullptr, g_hA,
             b_ih, b_hh, rowBase, nrows, 1, warp, lr, lk);
}

// ============ attn_tail: bf16 weights, concurrent sVn, register gate
#define AT_SMEM (80*72*2 + 64*72*2 + 64*72*2 + 128*72*2 + 256*4 + 80*4 + 3*256*4)
__global__ void __launch_bounds__(256) attn_tail(
    const float* __restrict__ W1, const float* __restrict__ W3,
    const float* __restrict__ b1, const float* __restrict__ b2,
    const float* __restrict__ qw, const float* __restrict__ qb,
    const float* __restrict__ b3, const float* __restrict__ item_emb,
    const int* __restrict__ pos, const int* __restrict__ neg,
    int S, int L, int nrows)
{
    extern __shared__ char smraw[];
    uint16_t* sH   = (uint16_t*)smraw;           // [80][72]
    uint16_t* sW2  = sH + 80 * 72;               // [64][72]
    uint16_t* sW1t = sW2 + 64 * 72;              // [64][72]: sW1t[k*72+c] = W1[c][k]
    uint16_t* sW3t = sW1t + 64 * 72;             // [128][72]: sW3t[k*72+c] = W3[c][k]
    float* sVn  = (float*)(sW3t + 128 * 72);     // [4][64]
    float* sAl  = sVn + 256;                     // [80]
    float* sSg  = sAl + 80;                      // [4][64]
    float* sVnF = sSg + 256;                     // [4][64]
    float* sSh  = sVnF + 256;                    // [4][64]

    int tid = threadIdx.x, lane = tid & 31, warp = tid >> 5;
    int lr = lane >> 2, lk = lane & 3;
    int s0 = blockIdx.x * 4;
    int rowBase = s0 * L;

    for (int i = tid; i < 64 * 8; i += 256) {
        int c = i >> 3, q = (i & 7) * 8;
        cp16(smem_u32(&sW2[c * 72 + q]), &g_w2Bb[c * 64 + q]);
    }
    asm volatile("cp.async.commit_group;");
    for (int i = tid; i < 80 * 8; i += 256) {
        int rl = i >> 3, seg = (i & 7) * 8;
        int gr = rowBase + rl;
        float4 v0 = make_float4(0.f,0.f,0.f,0.f), v1 = v0;
        if (gr < nrows) {
            v0 = *(const float4*)&g_hA[gr * 64 + seg];
            v1 = *(const float4*)&g_hA[gr * 64 + seg + 4];
        }
        uint32_t* dp = (uint32_t*)&sH[rl * 72 + seg];
        dp[0] = pbf2(v0.x, v0.y); dp[1] = pbf2(v0.z, v0.w);
        dp[2] = pbf2(v1.x, v1.y); dp[3] = pbf2(v1.z, v1.w);
    }
    for (int i = tid; i < 64 * 64; i += 256) {
        int c = i >> 6, k = i & 63;
        sW1t[k * 72 + c] = __bfloat16_as_ushort(__float2bfloat16_rn(__ldg(&W1[i])));
    }
    for (int i = tid; i < 64 * 128; i += 256) {
        int c = i >> 7, k = i & 127;
        sW3t[k * 72 + c] = __bfloat16_as_ushort(__float2bfloat16_rn(__ldg(&W3[i])));
    }
    asm volatile("cp.async.wait_group 0;");
    __syncthreads();

    // concurrent: warps 0-4 hW2 mma; warps 5-7 sVn
    float acc[8][4];
    if (warp < 5) {
        int r0 = warp * 16 + lr;
#pragma unroll
        for (int nt = 0; nt < 8; nt++)
#pragma unroll
            for (int q = 0; q < 4; q++) acc[nt][q] = 0.f;
#pragma unroll
        for (int k0 = 0; k0 < 64; k0 += 16) {
            uint32_t a[4];
            a[0] = *(const uint32_t*)&sH[r0 * 72 + k0 + 2 * lk];
            a[1] = *(const uint32_t*)&sH[(r0 + 8) * 72 + k0 + 2 * lk];
            a[2] = *(const uint32_t*)&sH[r0 * 72 + k0 + 8 + 2 * lk];
            a[3] = *(const uint32_t*)&sH[(r0 + 8) * 72 + k0 + 8 + 2 * lk];
#pragma unroll
            for (int nt = 0; nt < 8; nt++) {
                int c = nt * 8 + lr;
                uint32_t b0 = *(const uint32_t*)&sW2[c * 72 + k0 + 2 * lk];
                uint32_t b1 = *(const uint32_t*)&sW2[c * 72 + k0 + 8 + 2 * lk];
                mma_bf16(acc[nt], a, b0, b1);
            }
        }
    } else {
        for (int o = (warp - 5) * 32 + lane; o < 256; o += 96) {
            int sess = o >> 6, c = o & 63;
            int row = sess * L + L - 1;
            float a = 0.f;
#pragma unroll 8
            for (int k = 0; k < 64; k++)
                a = fmaf(bf2f(sH[row * 72 + k]), bf2f(sW1t[k * 72 + c]), a);
            sVn[o] = a;
        }
    }
    __syncthreads();

    // register gate epilogue (warps 0-4)
    if (warp < 5) {
        int ra = warp * 16 + lr, rb2 = ra + 8;
        int sa = ra / L, sb = rb2 / L;
        float al0 = 0.f, al1 = 0.f;
#pragma unroll
        for (int nt = 0; nt < 8; nt++) {
#pragma unroll
            for (int q = 0; q < 2; q++) {
                int c = nt * 8 + 2 * lk + q;
                float bb = __ldg(&b1[c]) + __ldg(&b2[c]);
                float qv = __ldg(&qw[c]);
                float x0 = acc[nt][q]     + sVn[sa * 64 + c] + bb;
                float x1 = acc[nt][2 + q] + sVn[sb * 64 + c] + bb;
                al0 = fmaf(fsigmoid(x0), qv, al0);
                al1 = fmaf(fsigmoid(x1), qv, al1);
            }
        }
        al0 += __shfl_xor_sync(0xffffffffu, al0, 1);
        al0 += __shfl_xor_sync(0xffffffffu, al0, 2);
        al1 += __shfl_xor_sync(0xffffffffu, al1, 1);
        al1 += __shfl_xor_sync(0xffffffffu, al1, 2);
        float qbv = __ldg(&qb[0]);
        if (lk == 0) { sAl[ra] = al0 + qbv; sAl[rb2] = al1 + qbv; }
    }
    __syncthreads();

    // s_g (bf16 sH) + exact fp32 v_n from gmem
    {
        int sess = tid >> 6, c = tid & 63;
        int rl0 = sess * L;
        float sg = 0.f;
        for (int i2 = 0; i2 < L; i2++)
            sg = fmaf(sAl[rl0 + i2], bf2f(sH[(rl0 + i2) * 72 + c]), sg);
        sSg[tid] = sg;
        int gvn = rowBase + rl0 + L - 1;
        sVnF[tid] = (gvn < nrows) ? g_hA[(size_t)gvn * 64 + c] : 0.f;
    }
    __syncthreads();

    // s_h = [vn | sg] @ W3^T + b3
    {
        int sess = tid >> 6, c = tid & 63;
        float a = __ldg(&b3[c]);
#pragma unroll 8
        for (int k = 0; k < 64; k++)
            a = fmaf(sVnF[sess * 64 + k], bf2f(sW3t[k * 72 + c]), a);
#pragma unroll 8
        for (int k = 0; k < 64; k++)
            a = fmaf(sSg[sess * 64 + k], bf2f(sW3t[(64 + k) * 72 + c]), a);
        sSh[tid] = a;
    }
    __syncthreads();

    // BPR loss (warp per session)
    if (warp < 4) {
        int gs = s0 + warp;
        if (gs < S) {
            int ip = __ldg(&pos[gs]), in2 = __ldg(&neg[gs]);
            float pp = 0.f, np = 0.f, rg = 0.f;
#pragma unroll
            for (int t = 0; t < 2; t++) {
                int j = lane + t * 32;
                float sv = sSh[warp * 64 + j];
                float pe = __ldg(&item_emb[(size_t)ip * 64 + j]);
                float ne = __ldg(&item_emb[(size_t)in2 * 64 + j]);
                pp = fmaf(sv, pe, pp);
                np = fmaf(sv, ne, np);
                rg += sv * sv + pe * pe + ne * ne;
            }
#pragma unroll
            for (int o = 16; o; o >>= 1) {
                pp += __shfl_xor_sync(0xffffffffu, pp, o);
                np += __shfl_xor_sync(0xffffffffu, np, o);
                rg += __shfl_xor_sync(0xffffffffu, rg, o);
            }
            if (lane == 0) {
                float x = pp - np;
                float lsm = (x > 0.f) ? log1pf(expf(-x)) : (-x + log1pf(expf(x)));
                atomicAdd(&g_acc[0], (double)lsm);
                atomicAdd(&g_acc[1], (double)rg);
            }
        }
    }
}

__global__ void finalize_kernel(float* out, int out_size)
{
    double loss = g_acc[0];
    double nr = g_acc[1] * 1e-5;
    float t = (float)(loss + nr), l = (float)loss, r = (float)nr;
    if (out_size > 0) out[0] = t;
    if (out_size > 1) out[1] = l;
    if (out_size > 2) out[2] = r;
    if (out_size > 3) out[3] = r;
    if (out_size > 4) out[4] = r;
}

// ---------------------------------------------------------------- host
extern "C" void kernel_launch(void* const* d_in, const int* in_sizes, int n_in,
                              void* d_out, int out_size)
{
    const float* item_emb = (const float*)d_in[0];
    const float* ggc      = (const float*)d_in[1];
    const float* W_ih     = (const float*)d_in[2];
    const float* b_ih     = (const float*)d_in[3];
    const float* W_hh     = (const float*)d_in[4];
    const float* b_hh     = (const float*)d_in[5];
    const float* W1       = (const float*)d_in[6];
    const float* b1       = (const float*)d_in[7];
    const float* W2       = (const float*)d_in[8];
    const float* b2       = (const float*)d_in[9];
    const float* qw       = (const float*)d_in[10];
    const float* qb       = (const float*)d_in[11];
    const float* W3       = (const float*)d_in[12];
    const float* b3       = (const float*)d_in[13];
    const int* node_items = (const int*)d_in[14];
    const int* edge_index = (const int*)d_in[15];
    const int* pos        = (const int*)d_in[17];
    const int* neg        = (const int*)d_in[18];

    int N = in_sizes[14];
    int E = in_sizes[15] / 2;
    int S = in_sizes[17];
    int L = N / S;
    float* out = (float*)d_out;

    cudaFuncSetAttribute(gnn2,      cudaFuncAttributeMaxDynamicSharedMemorySize, GNN_SMEM);
    cudaFuncSetAttribute(attn_tail, cudaFuncAttributeMaxDynamicSharedMemorySize, AT_SMEM);

    const int* src = edge_index;
    const int* dst = edge_index + E;

    init_all<<<(N + 255) / 256, 256>>>(W_ih, W_hh, ggc, W2, N);
    build_inedge_kernel<<<(E + 255) / 256, 256>>>(src, dst, E);

    gnn2<<<(N + 79) / 80, 256, GNN_SMEM>>>(b_ih, b_hh, N, item_emb, node_items);

    attn_tail<<<(S + 3) / 4, 256, AT_SMEM>>>(W1, W3, b1, b2, qw, qb, b3,
                                             item_emb, pos, neg, S, L, N);
    finalize_kernel<<<1, 1>>>(out, out_size);
}